// round 10
// baseline (speedup 1.0000x reference)
#include <cuda_runtime.h>
#include <cuda_bf16.h>
#include <cstdint>

#define BB 2
#define SS 2048
#define DD 512
#define LL 6
#define HH 8
#define FF 2048
#define VV 32000
#define ROWS (BB*SS)   // 4096

// fp32 residual stream scratch
__device__ float g_h [ROWS * DD];
__device__ float g_t [ROWS * DD];
// packed bf16 hi/lo activation planes
__device__ __align__(16) __nv_bfloat16 g_hh [ROWS * DD],  g_hl [ROWS * DD];
__device__ __align__(16) __nv_bfloat16 g_qh [ROWS * 3*DD], g_ql [ROWS * 3*DD];
__device__ __align__(16) __nv_bfloat16 g_oh [ROWS * DD],  g_ol [ROWS * DD];
__device__ __align__(16) __nv_bfloat16 g_fh [ROWS * FF],  g_fl [ROWS * FF];
__device__ __align__(16) __nv_bfloat16 g_th [ROWS * DD],  g_tl [ROWS * DD];
// pre-transposed bf16-split weights: [N][K] row-major
__device__ __align__(16) __nv_bfloat16 g_qkvT_h[LL * 3*DD * DD], g_qkvT_l[LL * 3*DD * DD];
__device__ __align__(16) __nv_bfloat16 g_woT_h [LL * DD * DD],   g_woT_l [LL * DD * DD];
__device__ __align__(16) __nv_bfloat16 g_w1T_h [LL * FF * DD],   g_w1T_l [LL * FF * DD];
__device__ __align__(16) __nv_bfloat16 g_w2T_h [LL * DD * FF],   g_w2T_l [LL * DD * FF];
__device__ __align__(16) __nv_bfloat16 g_outT_h[VV * DD],        g_outT_l[VV * DD];

extern __shared__ char dynsm[];

// ---------------------------------------------------------------------------
__device__ __forceinline__ uint32_t smem_u32(const void* p) {
    uint32_t a;
    asm("{ .reg .u64 t; cvta.to.shared.u64 t, %1; cvt.u32.u64 %0, t; }"
        : "=r"(a) : "l"(p));
    return a;
}
__device__ __forceinline__ void cpa16(uint32_t s, const void* g) {
    asm volatile("cp.async.cg.shared.global [%0], [%1], 16;" :: "r"(s), "l"(g));
}
__device__ __forceinline__ void split2(float x0, float x1, uint32_t& hw, uint32_t& lw) {
    __nv_bfloat16 h0 = __float2bfloat16(x0), h1 = __float2bfloat16(x1);
    __nv_bfloat16 l0 = __float2bfloat16(x0 - __bfloat162float(h0));
    __nv_bfloat16 l1 = __float2bfloat16(x1 - __bfloat162float(h1));
    __nv_bfloat162 hp(h0, h1), lp(l0, l1);
    hw = *(uint32_t*)&hp;
    lw = *(uint32_t*)&lp;
}
__device__ __forceinline__ void mma_bf16(float* d, const uint32_t* a, const uint32_t* b) {
    asm volatile("mma.sync.aligned.m16n8k16.row.col.f32.bf16.bf16.f32 "
        "{%0,%1,%2,%3}, {%4,%5,%6,%7}, {%8,%9}, {%0,%1,%2,%3};"
        : "+f"(d[0]), "+f"(d[1]), "+f"(d[2]), "+f"(d[3])
        : "r"(a[0]), "r"(a[1]), "r"(a[2]), "r"(a[3]), "r"(b[0]), "r"(b[1]));
}
__device__ __forceinline__ void ldm4(uint32_t* r, uint32_t a) {
    asm volatile("ldmatrix.sync.aligned.m8n8.x4.shared.b16 {%0,%1,%2,%3}, [%4];"
        : "=r"(r[0]), "=r"(r[1]), "=r"(r[2]), "=r"(r[3]) : "r"(a));
}
__device__ __forceinline__ void ldm4t(uint32_t* r, uint32_t a) {
    asm volatile("ldmatrix.sync.aligned.m8n8.x4.trans.shared.b16 {%0,%1,%2,%3}, [%4];"
        : "=r"(r[0]), "=r"(r[1]), "=r"(r[2]), "=r"(r[3]) : "r"(a));
}

// ---------------------------------------------------------------------------
// Weight prep: W[K,N] fp32 -> WT hi/lo [N,K] bf16
// ---------------------------------------------------------------------------
__global__ void wprep_k(const float* __restrict__ W, __nv_bfloat16* __restrict__ hi,
                        __nv_bfloat16* __restrict__ lo, int K, int N)
{
    __shared__ float ts[32][33];
    long moff = (long)blockIdx.z * K * N;
    int kb = blockIdx.y * 32, nb = blockIdx.x * 32;
    int r = threadIdx.x >> 5, c = threadIdx.x & 31;
    #pragma unroll
    for (int i = 0; i < 4; i++)
        ts[r + i*8][c] = W[moff + (long)(kb + r + i*8) * N + nb + c];
    __syncthreads();
    #pragma unroll
    for (int i = 0; i < 4; i++) {
        int n = r + i*8;
        float x = ts[c][n];
        __nv_bfloat16 h = __float2bfloat16(x);
        __nv_bfloat16 l = __float2bfloat16(x - __bfloat162float(h));
        long oidx = moff + (long)(nb + n) * K + kb + c;
        hi[oidx] = h;
        lo[oidx] = l;
    }
}

// ---------------------------------------------------------------------------
// Embedding + PE -> fp32 h + hi/lo planes
// ---------------------------------------------------------------------------
__global__ void embed_k(const int* __restrict__ x, const float* __restrict__ emb,
                        const float* __restrict__ pe, float* __restrict__ h,
                        uint32_t* __restrict__ oh, uint32_t* __restrict__ ol)
{
    int row = blockIdx.x, tid = threadIdx.x;
    int s   = row & (SS - 1);
    int tok = x[row];
    float4 ev = ((const float4*)(emb + (long)tok * DD))[tid];
    float4 pv = ((const float4*)(pe  + (long)s   * DD))[tid];
    float4 o;
    o.x = ev.x + pv.x; o.y = ev.y + pv.y; o.z = ev.z + pv.z; o.w = ev.w + pv.w;
    ((float4*)(h + (long)row * DD))[tid] = o;
    uint32_t hw, lw;
    int wi = row * (DD/2) + tid * 2;
    split2(o.x, o.y, hw, lw); oh[wi] = hw;   ol[wi] = lw;
    split2(o.z, o.w, hw, lw); oh[wi+1] = hw; ol[wi+1] = lw;
}

// ---------------------------------------------------------------------------
// out = LayerNorm(x (+ res)) * g + b -> fp32 + hi/lo planes
// ---------------------------------------------------------------------------
__global__ void add_ln_k(const float* __restrict__ x, const float* __restrict__ res,
                         const float* __restrict__ gg, const float* __restrict__ bb,
                         float* __restrict__ outF,
                         uint32_t* __restrict__ outH, uint32_t* __restrict__ outL)
{
    int row = blockIdx.x, tid = threadIdx.x;
    float4 v = ((const float4*)(x + (long)row * DD))[tid];
    if (res) {
        float4 rv = ((const float4*)(res + (long)row * DD))[tid];
        v.x += rv.x; v.y += rv.y; v.z += rv.z; v.w += rv.w;
    }
    float s  = v.x + v.y + v.z + v.w;
    float s2 = v.x*v.x + v.y*v.y + v.z*v.z + v.w*v.w;
    #pragma unroll
    for (int o = 16; o; o >>= 1) {
        s  += __shfl_xor_sync(0xffffffffu, s,  o);
        s2 += __shfl_xor_sync(0xffffffffu, s2, o);
    }
    __shared__ float ssum[4], ssq[4];
    int wid = tid >> 5;
    if ((tid & 31) == 0) { ssum[wid] = s; ssq[wid] = s2; }
    __syncthreads();
    s  = ssum[0] + ssum[1] + ssum[2] + ssum[3];
    s2 = ssq[0]  + ssq[1]  + ssq[2]  + ssq[3];
    float mean = s * (1.0f / DD);
    float var  = s2 * (1.0f / DD) - mean * mean;
    float inv  = rsqrtf(var + 1e-5f);
    float4 gv = ((const float4*)gg)[tid];
    float4 bv = ((const float4*)bb)[tid];
    float4 o;
    o.x = (v.x - mean) * inv * gv.x + bv.x;
    o.y = (v.y - mean) * inv * gv.y + bv.y;
    o.z = (v.z - mean) * inv * gv.z + bv.z;
    o.w = (v.w - mean) * inv * gv.w + bv.w;
    ((float4*)(outF + (long)row * DD))[tid] = o;
    uint32_t hw, lw;
    int wi = row * (DD/2) + tid * 2;
    split2(o.x, o.y, hw, lw); outH[wi] = hw;   outL[wi] = lw;
    split2(o.z, o.w, hw, lw); outH[wi+1] = hw; outL[wi+1] = lw;
}

// ---------------------------------------------------------------------------
// bf16 3-term tensor GEMM, 256 threads, 64x32 warp tile, BK=16,
// 12-word row stride (conflict-free), double-buffered, 2 CTAs/SM.
// ---------------------------------------------------------------------------
#define GSTR 12
#define GPL  (128*GSTR)            // 1536 words per plane
#define GEMM_SMEM (2*4*GPL*4)      // 49152 B

template<int RELU, int OUTMODE>
__global__ __launch_bounds__(256, 2)
void gemm_bf16(const __nv_bfloat16* __restrict__ Ahp, const __nv_bfloat16* __restrict__ Alp,
               const __nv_bfloat16* __restrict__ Bhp, const __nv_bfloat16* __restrict__ Blp,
               const float* __restrict__ bias,
               float* __restrict__ C, uint32_t* __restrict__ Chw, uint32_t* __restrict__ Clw,
               int M, int N, int K)
{
    uint32_t* sm = (uint32_t*)dynsm;
    const int tid = threadIdx.x, warp = tid >> 5, lane = tid & 31;
    const int g = lane >> 2, c = lane & 3;
    const int bm = blockIdx.x * 128, bn = blockIdx.y * 128;
    const int wm = (warp >> 2) * 64, wn = (warp & 3) * 32;
    const uint32_t sb = smem_u32(sm);
    const int T = K / 16;

    const int alr = lane & 15, alw = (lane >> 4) * 4;
    const int blr = (lane & 7) + ((lane >> 4) << 3);
    const int blw = ((lane >> 3) & 1) * 4;

    auto stage = [&](int t, int b) {
        int row = tid >> 1, half = tid & 1;
        uint32_t doff = (uint32_t)(row * GSTR + half * 4) * 4;
        uint32_t dbase = sb + (uint32_t)(b * 4 * GPL) * 4 + doff;
        long asrc = (long)(bm + row) * K + t * 16 + half * 8;
        long bsrc = (long)(bn + row) * K + t * 16 + half * 8;
        cpa16(dbase,             Ahp + asrc);
        cpa16(dbase + GPL*4,     Alp + asrc);
        cpa16(dbase + 2*GPL*4,   Bhp + bsrc);
        cpa16(dbase + 3*GPL*4,   Blp + bsrc);
        asm volatile("cp.async.commit_group;");
    };

    float acc[4][4][4] = {};

    stage(0, 0);
    if (T > 1) stage(1, 1);

    for (int t = 0; t < T; t++) {
        if (t + 1 < T) asm volatile("cp.async.wait_group 1;");
        else           asm volatile("cp.async.wait_group 0;");
        __syncthreads();

        const uint32_t bufb = sb + (uint32_t)((t & 1) * 4 * GPL) * 4;

        uint32_t ah[4][4], al[4][4];
        #pragma unroll
        for (int mt = 0; mt < 4; mt++) {
            uint32_t ao = (uint32_t)((wm + mt*16 + alr) * GSTR + alw) * 4;
            ldm4(ah[mt], bufb + ao);
            ldm4(al[mt], bufb + GPL*4 + ao);
        }
        #pragma unroll
        for (int pr = 0; pr < 2; pr++) {
            uint32_t bh[4], bl[4];
            uint32_t bo = (uint32_t)((wn + pr*16 + blr) * GSTR + blw) * 4;
            ldm4(bh, bufb + 2*GPL*4 + bo);
            ldm4(bl, bufb + 3*GPL*4 + bo);
            #pragma unroll
            for (int sub = 0; sub < 2; sub++) {
                int nt = pr * 2 + sub;
                #pragma unroll
                for (int mt = 0; mt < 4; mt++) {
                    mma_bf16(acc[mt][nt], ah[mt], bh + 2*sub);
                    mma_bf16(acc[mt][nt], ah[mt], bl + 2*sub);
                    mma_bf16(acc[mt][nt], al[mt], bh + 2*sub);
                }
            }
        }
        __syncthreads();
        if (t + 2 < T) stage(t + 2, t & 1);
    }

    #pragma unroll
    for (int mt = 0; mt < 4; mt++) {
        #pragma unroll
        for (int nt = 0; nt < 4; nt++) {
            int col = bn + wn + nt*8 + 2*c;
            float bx = 0.f, by = 0.f;
            if (bias) { bx = bias[col]; by = bias[col + 1]; }
            long r0 = bm + wm + mt*16 + g;
            float v0 = acc[mt][nt][0] + bx, v1 = acc[mt][nt][1] + by;
            float v2 = acc[mt][nt][2] + bx, v3 = acc[mt][nt][3] + by;
            if (RELU) {
                v0 = fmaxf(v0, 0.f); v1 = fmaxf(v1, 0.f);
                v2 = fmaxf(v2, 0.f); v3 = fmaxf(v3, 0.f);
            }
            if (OUTMODE == 0) {
                *(float2*)(C + r0 * N + col)       = make_float2(v0, v1);
                *(float2*)(C + (r0 + 8) * N + col) = make_float2(v2, v3);
            } else {
                uint32_t hw, lw;
                split2(v0, v1, hw, lw);
                Chw[(r0 * N + col) >> 1] = hw; Clw[(r0 * N + col) >> 1] = lw;
                split2(v2, v3, hw, lw);
                Chw[((r0 + 8) * N + col) >> 1] = hw; Clw[((r0 + 8) * N + col) >> 1] = lw;
            }
        }
    }
}

// ---------------------------------------------------------------------------
// mma flash attention (round-8 known-good version, single-buffered K/V).
// CTA = 128 q-rows x (head, batch), 8 warps x 16 rows.
// ---------------------------------------------------------------------------
#define ASTR 36
#define AQH 0
#define AQL (128*ASTR)
#define AKH (2*128*ASTR)
#define AKL (AKH + 64*ASTR)
#define AVH (AKH + 2*64*ASTR)
#define AVL (AKH + 3*64*ASTR)
#define ATT_SMEM ((2*128*ASTR + 4*64*ASTR)*4)   // 73728 B

__global__ __launch_bounds__(256)
void attn_mma(const __nv_bfloat16* __restrict__ qh, const __nv_bfloat16* __restrict__ ql,
              uint32_t* __restrict__ oh, uint32_t* __restrict__ ol)
{
    uint32_t* sm = (uint32_t*)dynsm;
    const uint32_t sb = smem_u32(sm);
    const int tid = threadIdx.x, warp = tid >> 5, lane = tid & 31;
    const int g = lane >> 2, c = lane & 3;
    const int qt = (int)gridDim.x - 1 - (int)blockIdx.x;
    const int h = blockIdx.y, b = blockIdx.z;
    const long rowbase = (long)b * SS;
    const int qoff = h << 6;

    const int alr = lane & 15, alw = (lane >> 4) * 4;
    const int blr = (lane & 7) + ((lane >> 4) << 3);
    const int blw = ((lane >> 3) & 1) * 4;
    const int vlr = ((lane >> 3) & 1) * 8 + (lane & 7);
    const int vlw = (lane >> 4) * 4;

    // stage Q (128 rows x 64, hi+lo)
    #pragma unroll
    for (int p = 0; p < 2; p++) {
        const __nv_bfloat16* src = p ? ql : qh;
        uint32_t dst = sb + (p ? AQL : AQH) * 4;
        #pragma unroll
        for (int i = 0; i < 4; i++) {
            int id = tid + 256 * i;
            int row = id >> 3, ch = id & 7;
            cpa16(dst + (uint32_t)(row * ASTR + ch * 4) * 4,
                  src + (rowbase + qt * 128 + row) * 1536 + qoff + ch * 8);
        }
    }
    asm volatile("cp.async.commit_group;");
    asm volatile("cp.async.wait_group 0;");
    __syncthreads();

    // hoist Q fragments (4 k-chunks x hi/lo)
    uint32_t Qh[4][4], Ql[4][4];
    #pragma unroll
    for (int kk = 0; kk < 4; kk++) {
        uint32_t qo = (uint32_t)((warp*16 + alr) * ASTR + kk*8 + alw) * 4;
        ldm4(Qh[kk], sb + AQH*4 + qo);
        ldm4(Ql[kk], sb + AQL*4 + qo);
    }

    float m0 = -1e30f, m1 = -1e30f, l0 = 0.f, l1 = 0.f;
    float O[8][4] = {};
    const int nk = 2 * qt + 2;
    const int rbase = qt * 128 + warp * 16;

    for (int kt = 0; kt < nk; kt++) {
        // stage K and V rows (hi+lo) via cp.async
        #pragma unroll
        for (int i = 0; i < 8; i++) {
            int id = tid + 256 * i;
            int p  = (id >> 9) & 1;
            int kv = id >> 10;
            int rem = id & 511;
            int row = rem >> 3, ch = rem & 7;
            const __nv_bfloat16* src = p ? ql : qh;
            uint32_t base = kv ? (p ? AVL : AVH) : (p ? AKL : AKH);
            cpa16(sb + (uint32_t)(base + row * ASTR + ch * 4) * 4,
                  src + (rowbase + kt * 64 + row) * 1536 + (kv ? 1024 : 512) + qoff + ch * 8);
        }
        asm volatile("cp.async.commit_group;");
        asm volatile("cp.async.wait_group 0;");
        __syncthreads();

        // ---- S = Q K^T ----
        float sacc[8][4] = {};
        #pragma unroll
        for (int kk = 0; kk < 4; kk++) {
            #pragma unroll
            for (int pr = 0; pr < 4; pr++) {
                uint32_t bh[4], bl[4];
                uint32_t bo = (uint32_t)((pr*16 + blr) * ASTR + kk*8 + blw) * 4;
                ldm4(bh, sb + AKH*4 + bo);
                ldm4(bl, sb + AKL*4 + bo);
                #pragma unroll
                for (int sub = 0; sub < 2; sub++) {
                    int nt = pr * 2 + sub;
                    mma_bf16(sacc[nt], Qh[kk], bh + 2*sub);
                    mma_bf16(sacc[nt], Qh[kk], bl + 2*sub);
                    mma_bf16(sacc[nt], Ql[kk], bh + 2*sub);
                }
            }
        }

        // ---- mask + online softmax ----
        const float scale = 0.125f;
        const bool diag = (kt >= 2 * qt);
        const int row0 = rbase + g, row1 = rbase + g + 8;
        const int colb = kt * 64 + 2 * c;
        float rm0 = -1e30f, rm1 = -1e30f;
        #pragma unroll
        for (int nt = 0; nt < 8; nt++) {
            int c0 = colb + nt * 8;
            float v0 = sacc[nt][0] * scale, v1 = sacc[nt][1] * scale;
            float v2 = sacc[nt][2] * scale, v3 = sacc[nt][3] * scale;
            if (diag) {
                if (c0     > row0) v0 = -1e30f;
                if (c0 + 1 > row0) v1 = -1e30f;
                if (c0     > row1) v2 = -1e30f;
                if (c0 + 1 > row1) v3 = -1e30f;
            }
            sacc[nt][0] = v0; sacc[nt][1] = v1; sacc[nt][2] = v2; sacc[nt][3] = v3;
            rm0 = fmaxf(rm0, fmaxf(v0, v1));
            rm1 = fmaxf(rm1, fmaxf(v2, v3));
        }
        #pragma unroll
        for (int o = 1; o < 4; o <<= 1) {
            rm0 = fmaxf(rm0, __shfl_xor_sync(0xffffffffu, rm0, o));
            rm1 = fmaxf(rm1, __shfl_xor_sync(0xffffffffu, rm1, o));
        }
        float nm0 = fmaxf(m0, rm0), nm1 = fmaxf(m1, rm1);
        float sf0 = __expf(m0 - nm0), sf1 = __expf(m1 - nm1);
        m0 = nm0; m1 = nm1;
        float rs0 = 0.f, rs1 = 0.f;
        #pragma unroll
        for (int nt = 0; nt < 8; nt++) {
            float p0 = __expf(sacc[nt][0] - nm0);
            float p1 = __expf(sacc[nt][1] - nm0);
            float p2 = __expf(sacc[nt][2] - nm1);
            float p3 = __expf(sacc[nt][3] - nm1);
            sacc[nt][0] = p0; sacc[nt][1] = p1; sacc[nt][2] = p2; sacc[nt][3] = p3;
            rs0 += p0 + p1; rs1 += p2 + p3;
        }
        #pragma unroll
        for (int o = 1; o < 4; o <<= 1) {
            rs0 += __shfl_xor_sync(0xffffffffu, rs0, o);
            rs1 += __shfl_xor_sync(0xffffffffu, rs1, o);
        }
        l0 = l0 * sf0 + rs0;
        l1 = l1 * sf1 + rs1;
        #pragma unroll
        for (int nt = 0; nt < 8; nt++) {
            O[nt][0] *= sf0; O[nt][1] *= sf0;
            O[nt][2] *= sf1; O[nt][3] *= sf1;
        }

        // ---- O += P V ----
        #pragma unroll
        for (int kk = 0; kk < 4; kk++) {
            uint32_t ah[4], al[4];
            split2(sacc[2*kk][0],   sacc[2*kk][1],   ah[0], al[0]);
            split2(sacc[2*kk][2],   sacc[2*kk][3],   ah[1], al[1]);
            split2(sacc[2*kk+1][0], sacc[2*kk+1][1], ah[2], al[2]);
            split2(sacc[2*kk+1][2], sacc[2*kk+1][3], ah[3], al[3]);
            #pragma unroll
            for (int pr = 0; pr < 4; pr++) {
                uint32_t bh[4], bl[4];
                uint32_t vo = (uint32_t)((kk*16 + vlr) * ASTR + pr*8 + vlw) * 4;
                ldm4t(bh, sb + AVH*4 + vo);
                ldm4t(bl, sb + AVL*4 + vo);
                #pragma unroll
                for (int sub = 0; sub < 2; sub++) {
                    int nt = pr * 2 + sub;
                    mma_bf16(O[nt], ah, bh + 2*sub);
                    mma_bf16(O[nt], ah, bl + 2*sub);
                    mma_bf16(O[nt], al, bh + 2*sub);
                }
            }
        }
        __syncthreads();
    }

    // ---- epilogue ----
    float inv0 = 1.0f / l0, inv1 = 1.0f / l1;
    long grow0 = rowbase + rbase + g;
    #pragma unroll
    for (int nt = 0; nt < 8; nt++) {
        int col = qoff + nt * 8 + 2 * c;
        uint32_t hw, lw;
        split2(O[nt][0] * inv0, O[nt][1] * inv0, hw, lw);
        oh[(grow0 * DD + col) >> 1] = hw;
        ol[(grow0 * DD + col) >> 1] = lw;
        split2(O[nt][2] * inv1, O[nt][3] * inv1, hw, lw);
        oh[((grow0 + 8) * DD + col) >> 1] = hw;
        ol[((grow0 + 8) * DD + col) >> 1] = lw;
    }
}

// ---------------------------------------------------------------------------
extern "C" void kernel_launch(void* const* d_in, const int* in_sizes, int n_in,
                              void* d_out, int out_size)
{
    const int*   x    = (const int*)  d_in[0];
    const float* emb  = (const float*)d_in[1];
    const float* pe   = (const float*)d_in[2];
    const float* Wqkv = (const float*)d_in[3];
    const float* Wo   = (const float*)d_in[4];
    const float* bo   = (const float*)d_in[5];
    const float* g1   = (const float*)d_in[6];
    const float* b1   = (const float*)d_in[7];
    const float* g2   = (const float*)d_in[8];
    const float* b2   = (const float*)d_in[9];
    const float* W1   = (const float*)d_in[10];
    const float* bf1  = (const float*)d_in[11];
    const float* W2   = (const float*)d_in[12];
    const float* bf2  = (const float*)d_in[13];
    const float* gf   = (const float*)d_in[14];
    const float* bfp  = (const float*)d_in[15];
    const float* Wout = (const float*)d_in[16];
    const float* bfc  = (const float*)d_in[17];
    float* out = (float*)d_out;

    float *h, *t;
    cudaGetSymbolAddress((void**)&h, g_h);
    cudaGetSymbolAddress((void**)&t, g_t);
    __nv_bfloat16 *hh, *hl, *qh, *ql, *oh, *ol, *fh, *fl, *th, *tl;
    cudaGetSymbolAddress((void**)&hh, g_hh);  cudaGetSymbolAddress((void**)&hl, g_hl);
    cudaGetSymbolAddress((void**)&qh, g_qh);  cudaGetSymbolAddress((void**)&ql, g_ql);
    cudaGetSymbolAddress((void**)&oh, g_oh);  cudaGetSymbolAddress((void**)&ol, g_ol);
    cudaGetSymbolAddress((void**)&fh, g_fh);  cudaGetSymbolAddress((void**)&fl, g_fl);
    cudaGetSymbolAddress((void**)&th, g_th);  cudaGetSymbolAddress((void**)&tl, g_tl);
    __nv_bfloat16 *qkvTh, *qkvTl, *woTh, *woTl, *w1Th, *w1Tl, *w2Th, *w2Tl, *outTh, *outTl;
    cudaGetSymbolAddress((void**)&qkvTh, g_qkvT_h);
    cudaGetSymbolAddress((void**)&qkvTl, g_qkvT_l);
    cudaGetSymbolAddress((void**)&woTh,  g_woT_h);
    cudaGetSymbolAddress((void**)&woTl,  g_woT_l);
    cudaGetSymbolAddress((void**)&w1Th,  g_w1T_h);
    cudaGetSymbolAddress((void**)&w1Tl,  g_w1T_l);
    cudaGetSymbolAddress((void**)&w2Th,  g_w2T_h);
    cudaGetSymbolAddress((void**)&w2Tl,  g_w2T_l);
    cudaGetSymbolAddress((void**)&outTh, g_outT_h);
    cudaGetSymbolAddress((void**)&outTl, g_outT_l);

    cudaFuncSetAttribute(attn_mma, cudaFuncAttributeMaxDynamicSharedMemorySize, ATT_SMEM);
    cudaFuncSetAttribute(gemm_bf16<0,0>, cudaFuncAttributeMaxDynamicSharedMemorySize, GEMM_SMEM);
    cudaFuncSetAttribute(gemm_bf16<0,1>, cudaFuncAttributeMaxDynamicSharedMemorySize, GEMM_SMEM);
    cudaFuncSetAttribute(gemm_bf16<1,1>, cudaFuncAttributeMaxDynamicSharedMemorySize, GEMM_SMEM);

    wprep_k<<<dim3(3*DD/32, DD/32, LL), 256>>>(Wqkv, qkvTh, qkvTl, DD, 3*DD);
    wprep_k<<<dim3(DD/32,   DD/32, LL), 256>>>(Wo,   woTh,  woTl,  DD, DD);
    wprep_k<<<dim3(FF/32,   DD/32, LL), 256>>>(W1,   w1Th,  w1Tl,  DD, FF);
    wprep_k<<<dim3(DD/32,   FF/32, LL), 256>>>(W2,   w2Th,  w2Tl,  FF, DD);
    wprep_k<<<dim3(VV/32,   DD/32, 1 ), 256>>>(Wout, outTh, outTl, DD, VV);

    embed_k<<<ROWS, 128>>>(x, emb, pe, h, (uint32_t*)hh, (uint32_t*)hl);

    for (int l = 0; l < LL; l++) {
        gemm_bf16<0,1><<<dim3(32, 12), 256, GEMM_SMEM>>>(
            hh, hl, qkvTh + (long)l * 3*DD*DD, qkvTl + (long)l * 3*DD*DD,
            nullptr, nullptr, (uint32_t*)qh, (uint32_t*)ql, ROWS, 3*DD, DD);
        attn_mma<<<dim3(SS/128, HH, BB), 256, ATT_SMEM>>>(
            qh, ql, (uint32_t*)oh, (uint32_t*)ol);
        gemm_bf16<0,0><<<dim3(32, 4), 256, GEMM_SMEM>>>(
            oh, ol, woTh + (long)l * DD*DD, woTl + (long)l * DD*DD,
            bo + l * DD, t, nullptr, nullptr, ROWS, DD, DD);
        add_ln_k<<<ROWS, 128>>>(t, h, g1 + l * DD, b1 + l * DD,
                                h, (uint32_t*)hh, (uint32_t*)hl);
        gemm_bf16<1,1><<<dim3(32, 16), 256, GEMM_SMEM>>>(
            hh, hl, w1Th + (long)l * FF*DD, w1Tl + (long)l * FF*DD,
            bf1 + l * FF, nullptr, (uint32_t*)fh, (uint32_t*)fl, ROWS, FF, DD);
        gemm_bf16<0,0><<<dim3(32, 4), 256, GEMM_SMEM>>>(
            fh, fl, w2Th + (long)l * DD*FF, w2Tl + (long)l * DD*FF,
            bf2 + l * DD, t, nullptr, nullptr, ROWS, DD, FF);
        add_ln_k<<<ROWS, 128>>>(t, h, g2 + l * DD, b2 + l * DD,
                                h, (uint32_t*)hh, (uint32_t*)hl);
    }

    add_ln_k<<<ROWS, 128>>>(h, nullptr, gf, bfp, t, (uint32_t*)th, (uint32_t*)tl);
    gemm_bf16<0,0><<<dim3(32, 250), 256, GEMM_SMEM>>>(
        th, tl, outTh, outTl, bfc, out, nullptr, nullptr, ROWS, VV, DD);
}

// round 11
// speedup vs baseline: 1.6029x; 1.6029x over previous
#include <cuda_runtime.h>
#include <cuda_bf16.h>
#include <cstdint>

#define BB 2
#define SS 2048
#define DD 512
#define LL 6
#define HH 8
#define FF 2048
#define VV 32000
#define ROWS (BB*SS)   // 4096

// fp32 residual stream scratch
__device__ float g_h [ROWS * DD];
__device__ float g_t [ROWS * DD];
// packed bf16 hi/lo activation planes
__device__ __align__(16) __nv_bfloat16 g_hh [ROWS * DD],  g_hl [ROWS * DD];
__device__ __align__(16) __nv_bfloat16 g_qh [ROWS * 3*DD], g_ql [ROWS * 3*DD];
__device__ __align__(16) __nv_bfloat16 g_oh [ROWS * DD],  g_ol [ROWS * DD];
__device__ __align__(16) __nv_bfloat16 g_fh [ROWS * FF],  g_fl [ROWS * FF];
__device__ __align__(16) __nv_bfloat16 g_th [ROWS * DD],  g_tl [ROWS * DD];
// pre-transposed bf16-split weights: [N][K] row-major
__device__ __align__(16) __nv_bfloat16 g_qkvT_h[LL * 3*DD * DD], g_qkvT_l[LL * 3*DD * DD];
__device__ __align__(16) __nv_bfloat16 g_woT_h [LL * DD * DD],   g_woT_l [LL * DD * DD];
__device__ __align__(16) __nv_bfloat16 g_w1T_h [LL * FF * DD],   g_w1T_l [LL * FF * DD];
__device__ __align__(16) __nv_bfloat16 g_w2T_h [LL * DD * FF],   g_w2T_l [LL * DD * FF];
__device__ __align__(16) __nv_bfloat16 g_outT_h[VV * DD],        g_outT_l[VV * DD];

extern __shared__ char dynsm[];

// ---------------------------------------------------------------------------
__device__ __forceinline__ uint32_t smem_u32(const void* p) {
    uint32_t a;
    asm("{ .reg .u64 t; cvta.to.shared.u64 t, %1; cvt.u32.u64 %0, t; }"
        : "=r"(a) : "l"(p));
    return a;
}
__device__ __forceinline__ void cpa16(uint32_t s, const void* g) {
    asm volatile("cp.async.cg.shared.global [%0], [%1], 16;" :: "r"(s), "l"(g));
}
__device__ __forceinline__ void split2(float x0, float x1, uint32_t& hw, uint32_t& lw) {
    __nv_bfloat16 h0 = __float2bfloat16(x0), h1 = __float2bfloat16(x1);
    __nv_bfloat16 l0 = __float2bfloat16(x0 - __bfloat162float(h0));
    __nv_bfloat16 l1 = __float2bfloat16(x1 - __bfloat162float(h1));
    __nv_bfloat162 hp(h0, h1), lp(l0, l1);
    hw = *(uint32_t*)&hp;
    lw = *(uint32_t*)&lp;
}
__device__ __forceinline__ void mma_bf16(float* d, const uint32_t* a, const uint32_t* b) {
    asm volatile("mma.sync.aligned.m16n8k16.row.col.f32.bf16.bf16.f32 "
        "{%0,%1,%2,%3}, {%4,%5,%6,%7}, {%8,%9}, {%0,%1,%2,%3};"
        : "+f"(d[0]), "+f"(d[1]), "+f"(d[2]), "+f"(d[3])
        : "r"(a[0]), "r"(a[1]), "r"(a[2]), "r"(a[3]), "r"(b[0]), "r"(b[1]));
}
__device__ __forceinline__ void ldm4(uint32_t* r, uint32_t a) {
    asm volatile("ldmatrix.sync.aligned.m8n8.x4.shared.b16 {%0,%1,%2,%3}, [%4];"
        : "=r"(r[0]), "=r"(r[1]), "=r"(r[2]), "=r"(r[3]) : "r"(a));
}
__device__ __forceinline__ void ldm4t(uint32_t* r, uint32_t a) {
    asm volatile("ldmatrix.sync.aligned.m8n8.x4.trans.shared.b16 {%0,%1,%2,%3}, [%4];"
        : "=r"(r[0]), "=r"(r[1]), "=r"(r[2]), "=r"(r[3]) : "r"(a));
}

// ---------------------------------------------------------------------------
// Weight prep: W[K,N] fp32 -> WT hi/lo [N,K] bf16
// ---------------------------------------------------------------------------
__global__ void wprep_k(const float* __restrict__ W, __nv_bfloat16* __restrict__ hi,
                        __nv_bfloat16* __restrict__ lo, int K, int N)
{
    __shared__ float ts[32][33];
    long moff = (long)blockIdx.z * K * N;
    int kb = blockIdx.y * 32, nb = blockIdx.x * 32;
    int r = threadIdx.x >> 5, c = threadIdx.x & 31;
    #pragma unroll
    for (int i = 0; i < 4; i++)
        ts[r + i*8][c] = W[moff + (long)(kb + r + i*8) * N + nb + c];
    __syncthreads();
    #pragma unroll
    for (int i = 0; i < 4; i++) {
        int n = r + i*8;
        float x = ts[c][n];
        __nv_bfloat16 h = __float2bfloat16(x);
        __nv_bfloat16 l = __float2bfloat16(x - __bfloat162float(h));
        long oidx = moff + (long)(nb + n) * K + kb + c;
        hi[oidx] = h;
        lo[oidx] = l;
    }
}

// ---------------------------------------------------------------------------
// Embedding + PE -> fp32 h + hi/lo planes
// ---------------------------------------------------------------------------
__global__ void embed_k(const int* __restrict__ x, const float* __restrict__ emb,
                        const float* __restrict__ pe, float* __restrict__ h,
                        uint32_t* __restrict__ oh, uint32_t* __restrict__ ol)
{
    int row = blockIdx.x, tid = threadIdx.x;
    int s   = row & (SS - 1);
    int tok = x[row];
    float4 ev = ((const float4*)(emb + (long)tok * DD))[tid];
    float4 pv = ((const float4*)(pe  + (long)s   * DD))[tid];
    float4 o;
    o.x = ev.x + pv.x; o.y = ev.y + pv.y; o.z = ev.z + pv.z; o.w = ev.w + pv.w;
    ((float4*)(h + (long)row * DD))[tid] = o;
    uint32_t hw, lw;
    int wi = row * (DD/2) + tid * 2;
    split2(o.x, o.y, hw, lw); oh[wi] = hw;   ol[wi] = lw;
    split2(o.z, o.w, hw, lw); oh[wi+1] = hw; ol[wi+1] = lw;
}

// ---------------------------------------------------------------------------
// out = LayerNorm(x (+ res)) * g + b -> fp32 + hi/lo planes
// ---------------------------------------------------------------------------
__global__ void add_ln_k(const float* __restrict__ x, const float* __restrict__ res,
                         const float* __restrict__ gg, const float* __restrict__ bb,
                         float* __restrict__ outF,
                         uint32_t* __restrict__ outH, uint32_t* __restrict__ outL)
{
    int row = blockIdx.x, tid = threadIdx.x;
    float4 v = ((const float4*)(x + (long)row * DD))[tid];
    if (res) {
        float4 rv = ((const float4*)(res + (long)row * DD))[tid];
        v.x += rv.x; v.y += rv.y; v.z += rv.z; v.w += rv.w;
    }
    float s  = v.x + v.y + v.z + v.w;
    float s2 = v.x*v.x + v.y*v.y + v.z*v.z + v.w*v.w;
    #pragma unroll
    for (int o = 16; o; o >>= 1) {
        s  += __shfl_xor_sync(0xffffffffu, s,  o);
        s2 += __shfl_xor_sync(0xffffffffu, s2, o);
    }
    __shared__ float ssum[4], ssq[4];
    int wid = tid >> 5;
    if ((tid & 31) == 0) { ssum[wid] = s; ssq[wid] = s2; }
    __syncthreads();
    s  = ssum[0] + ssum[1] + ssum[2] + ssum[3];
    s2 = ssq[0]  + ssq[1]  + ssq[2]  + ssq[3];
    float mean = s * (1.0f / DD);
    float var  = s2 * (1.0f / DD) - mean * mean;
    float inv  = rsqrtf(var + 1e-5f);
    float4 gv = ((const float4*)gg)[tid];
    float4 bv = ((const float4*)bb)[tid];
    float4 o;
    o.x = (v.x - mean) * inv * gv.x + bv.x;
    o.y = (v.y - mean) * inv * gv.y + bv.y;
    o.z = (v.z - mean) * inv * gv.z + bv.z;
    o.w = (v.w - mean) * inv * gv.w + bv.w;
    ((float4*)(outF + (long)row * DD))[tid] = o;
    uint32_t hw, lw;
    int wi = row * (DD/2) + tid * 2;
    split2(o.x, o.y, hw, lw); outH[wi] = hw;   outL[wi] = lw;
    split2(o.z, o.w, hw, lw); outH[wi+1] = hw; outL[wi+1] = lw;
}

// ---------------------------------------------------------------------------
// bf16 3-term tensor GEMM: 256 threads, 64x32 warp tile, BK=32,
// 3-stage cp.async pipeline, ONE __syncthreads per K-tile.
// ---------------------------------------------------------------------------
#define GSTR 20
#define GPL  (128*GSTR)            // words per plane
#define GBUF (4*GPL)               // words per buffer (Ah,Al,Bh,Bl)
#define GEMM_SMEM (3*GBUF*4)       // 122880 B

template<int RELU, int OUTMODE>
__global__ __launch_bounds__(256)
void gemm_bf16(const __nv_bfloat16* __restrict__ Ahp, const __nv_bfloat16* __restrict__ Alp,
               const __nv_bfloat16* __restrict__ Bhp, const __nv_bfloat16* __restrict__ Blp,
               const float* __restrict__ bias,
               float* __restrict__ C, uint32_t* __restrict__ Chw, uint32_t* __restrict__ Clw,
               int M, int N, int K)
{
    uint32_t* sm = (uint32_t*)dynsm;
    const int tid = threadIdx.x, warp = tid >> 5, lane = tid & 31;
    const int g = lane >> 2, c = lane & 3;
    const int bm = blockIdx.x * 128, bn = blockIdx.y * 128;
    const int wm = (warp >> 2) * 64, wn = (warp & 3) * 32;
    const uint32_t sb = smem_u32(sm);
    const int T = K / 32;

    const int alr = lane & 15, alw = (lane >> 4) * 4;
    const int blr = (lane & 7) + ((lane >> 4) << 3);
    const int blw = ((lane >> 3) & 1) * 4;

    auto stage = [&](int t, int b) {
        #pragma unroll
        for (int i = 0; i < 2; i++) {
            int id = tid + 256 * i, row = id >> 2, cc = id & 3;
            uint32_t doff = (uint32_t)(row * GSTR + cc * 4) * 4;
            uint32_t dbase = sb + (uint32_t)(b * GBUF) * 4 + doff;
            long asrc = (long)(bm + row) * K + t * 32 + cc * 8;
            long bsrc = (long)(bn + row) * K + t * 32 + cc * 8;
            cpa16(dbase,             Ahp + asrc);
            cpa16(dbase + GPL*4,     Alp + asrc);
            cpa16(dbase + 2*GPL*4,   Bhp + bsrc);
            cpa16(dbase + 3*GPL*4,   Blp + bsrc);
        }
        asm volatile("cp.async.commit_group;");
    };

    float acc[4][4][4] = {};

    stage(0, 0);
    if (T > 1) stage(1, 1);

    for (int t = 0; t < T; t++) {
        if (t + 1 < T) asm volatile("cp.async.wait_group 1;");
        else           asm volatile("cp.async.wait_group 0;");
        __syncthreads();
        // buffer (t+2)%3 was consumed at iteration t-1; safe to refill now
        if (t + 2 < T) stage(t + 2, (t + 2) % 3);

        const uint32_t bufb = sb + (uint32_t)((t % 3) * GBUF) * 4;

        #pragma unroll
        for (int kk = 0; kk < 2; kk++) {
            uint32_t ah[4][4], al[4][4];
            #pragma unroll
            for (int mt = 0; mt < 4; mt++) {
                uint32_t ao = (uint32_t)((wm + mt*16 + alr) * GSTR + kk*8 + alw) * 4;
                ldm4(ah[mt], bufb + ao);
                ldm4(al[mt], bufb + GPL*4 + ao);
            }
            #pragma unroll
            for (int pr = 0; pr < 2; pr++) {
                uint32_t bh[4], bl[4];
                uint32_t bo = (uint32_t)((wn + pr*16 + blr) * GSTR + kk*8 + blw) * 4;
                ldm4(bh, bufb + 2*GPL*4 + bo);
                ldm4(bl, bufb + 3*GPL*4 + bo);
                #pragma unroll
                for (int sub = 0; sub < 2; sub++) {
                    int nt = pr * 2 + sub;
                    #pragma unroll
                    for (int mt = 0; mt < 4; mt++) {
                        mma_bf16(acc[mt][nt], ah[mt], bh + 2*sub);
                        mma_bf16(acc[mt][nt], ah[mt], bl + 2*sub);
                        mma_bf16(acc[mt][nt], al[mt], bh + 2*sub);
                    }
                }
            }
        }
    }

    #pragma unroll
    for (int mt = 0; mt < 4; mt++) {
        #pragma unroll
        for (int nt = 0; nt < 4; nt++) {
            int col = bn + wn + nt*8 + 2*c;
            float bx = 0.f, by = 0.f;
            if (bias) { bx = bias[col]; by = bias[col + 1]; }
            long r0 = bm + wm + mt*16 + g;
            float v0 = acc[mt][nt][0] + bx, v1 = acc[mt][nt][1] + by;
            float v2 = acc[mt][nt][2] + bx, v3 = acc[mt][nt][3] + by;
            if (RELU) {
                v0 = fmaxf(v0, 0.f); v1 = fmaxf(v1, 0.f);
                v2 = fmaxf(v2, 0.f); v3 = fmaxf(v3, 0.f);
            }
            if (OUTMODE == 0) {
                *(float2*)(C + r0 * N + col)       = make_float2(v0, v1);
                *(float2*)(C + (r0 + 8) * N + col) = make_float2(v2, v3);
            } else {
                uint32_t hw, lw;
                split2(v0, v1, hw, lw);
                Chw[(r0 * N + col) >> 1] = hw; Clw[(r0 * N + col) >> 1] = lw;
                split2(v2, v3, hw, lw);
                Chw[((r0 + 8) * N + col) >> 1] = hw; Clw[((r0 + 8) * N + col) >> 1] = lw;
            }
        }
    }
}

// ---------------------------------------------------------------------------
// mma flash attention, double-buffered K/V, ONE __syncthreads per k-tile.
// CTA = 128 q-rows x (head, batch), 8 warps x 16 rows.
// ---------------------------------------------------------------------------
#define ASTR 36
#define AQH 0
#define AQL (128*ASTR)          // 4608 words
#define KVB (2*128*ASTR)        // 9216 words: start of KV buffers
#define KVSZ (4*64*ASTR)        // 9216 words per KV buffer (KH,KL,VH,VL)
#define ATT_SMEM ((KVB + 2*KVSZ)*4)   // 110592 B

__global__ __launch_bounds__(256)
void attn_mma(const __nv_bfloat16* __restrict__ qh, const __nv_bfloat16* __restrict__ ql,
              uint32_t* __restrict__ oh, uint32_t* __restrict__ ol)
{
    uint32_t* sm = (uint32_t*)dynsm;
    const uint32_t sb = smem_u32(sm);
    const int tid = threadIdx.x, warp = tid >> 5, lane = tid & 31;
    const int g = lane >> 2, c = lane & 3;
    const int qt = (int)gridDim.x - 1 - (int)blockIdx.x;
    const int h = blockIdx.y, b = blockIdx.z;
    const long rowbase = (long)b * SS;
    const int qoff = h << 6;

    const int alr = lane & 15, alw = (lane >> 4) * 4;
    const int blr = (lane & 7) + ((lane >> 4) << 3);
    const int blw = ((lane >> 3) & 1) * 4;
    const int vlr = ((lane >> 3) & 1) * 8 + (lane & 7);
    const int vlw = (lane >> 4) * 4;

    auto stage_kv = [&](int kt, int bsel) {
        uint32_t kvbase = KVB + bsel * KVSZ;
        #pragma unroll
        for (int i = 0; i < 8; i++) {
            int id = tid + 256 * i;
            int p  = (id >> 9) & 1;
            int kv = id >> 10;
            int rem = id & 511;
            int row = rem >> 3, ch = rem & 7;
            const __nv_bfloat16* src = p ? ql : qh;
            uint32_t off = kvbase + (kv ? 2*2304 : 0) + (p ? 2304 : 0) + row * ASTR + ch * 4;
            cpa16(sb + off * 4,
                  src + (rowbase + kt * 64 + row) * 1536 + (kv ? 1024 : 512) + qoff + ch * 8);
        }
        asm volatile("cp.async.commit_group;");
    };

    // stage Q (128 rows x 64, hi+lo) and first KV tile
    #pragma unroll
    for (int p = 0; p < 2; p++) {
        const __nv_bfloat16* src = p ? ql : qh;
        uint32_t dst = sb + (p ? AQL : AQH) * 4;
        #pragma unroll
        for (int i = 0; i < 4; i++) {
            int id = tid + 256 * i;
            int row = id >> 3, ch = id & 7;
            cpa16(dst + (uint32_t)(row * ASTR + ch * 4) * 4,
                  src + (rowbase + qt * 128 + row) * 1536 + qoff + ch * 8);
        }
    }
    asm volatile("cp.async.commit_group;");
    stage_kv(0, 0);
    asm volatile("cp.async.wait_group 0;");
    __syncthreads();

    // hoist Q fragments (4 k-chunks x hi/lo)
    uint32_t Qh[4][4], Ql[4][4];
    #pragma unroll
    for (int kk = 0; kk < 4; kk++) {
        uint32_t qo = (uint32_t)((warp*16 + alr) * ASTR + kk*8 + alw) * 4;
        ldm4(Qh[kk], sb + AQH*4 + qo);
        ldm4(Ql[kk], sb + AQL*4 + qo);
    }

    float m0 = -1e30f, m1 = -1e30f, l0 = 0.f, l1 = 0.f;
    float O[8][4] = {};
    const int nk = 2 * qt + 2;
    const int rbase = qt * 128 + warp * 16;

    for (int kt = 0; kt < nk; kt++) {
        asm volatile("cp.async.wait_group 0;");
        __syncthreads();
        // buffer (kt+1)&1 was consumed at kt-1; safe to refill; copy overlaps compute
        if (kt + 1 < nk) stage_kv(kt + 1, (kt + 1) & 1);

        const uint32_t kbuf = KVB + (uint32_t)((kt & 1) * KVSZ);
        const uint32_t KHb = sb + kbuf * 4;
        const uint32_t KLb = KHb + 2304 * 4;
        const uint32_t VHb = KHb + 4608 * 4;
        const uint32_t VLb = KHb + 6912 * 4;

        // ---- S = Q K^T ----
        float sacc[8][4] = {};
        #pragma unroll
        for (int kk = 0; kk < 4; kk++) {
            #pragma unroll
            for (int pr = 0; pr < 4; pr++) {
                uint32_t bh[4], bl[4];
                uint32_t bo = (uint32_t)((pr*16 + blr) * ASTR + kk*8 + blw) * 4;
                ldm4(bh, KHb + bo);
                ldm4(bl, KLb + bo);
                #pragma unroll
                for (int sub = 0; sub < 2; sub++) {
                    int nt = pr * 2 + sub;
                    mma_bf16(sacc[nt], Qh[kk], bh + 2*sub);
                    mma_bf16(sacc[nt], Qh[kk], bl + 2*sub);
                    mma_bf16(sacc[nt], Ql[kk], bh + 2*sub);
                }
            }
        }

        // ---- mask + online softmax ----
        const float scale = 0.125f;
        const bool diag = (kt >= 2 * qt);
        const int row0 = rbase + g, row1 = rbase + g + 8;
        const int colb = kt * 64 + 2 * c;
        float rm0 = -1e30f, rm1 = -1e30f;
        #pragma unroll
        for (int nt = 0; nt < 8; nt++) {
            int c0 = colb + nt * 8;
            float v0 = sacc[nt][0] * scale, v1 = sacc[nt][1] * scale;
            float v2 = sacc[nt][2] * scale, v3 = sacc[nt][3] * scale;
            if (diag) {
                if (c0     > row0) v0 = -1e30f;
                if (c0 + 1 > row0) v1 = -1e30f;
                if (c0     > row1) v2 = -1e30f;
                if (c0 + 1 > row1) v3 = -1e30f;
            }
            sacc[nt][0] = v0; sacc[nt][1] = v1; sacc[nt][2] = v2; sacc[nt][3] = v3;
            rm0 = fmaxf(rm0, fmaxf(v0, v1));
            rm1 = fmaxf(rm1, fmaxf(v2, v3));
        }
        #pragma unroll
        for (int o = 1; o < 4; o <<= 1) {
            rm0 = fmaxf(rm0, __shfl_xor_sync(0xffffffffu, rm0, o));
            rm1 = fmaxf(rm1, __shfl_xor_sync(0xffffffffu, rm1, o));
        }
        float nm0 = fmaxf(m0, rm0), nm1 = fmaxf(m1, rm1);
        float sf0 = __expf(m0 - nm0), sf1 = __expf(m1 - nm1);
        m0 = nm0; m1 = nm1;
        float rs0 = 0.f, rs1 = 0.f;
        #pragma unroll
        for (int nt = 0; nt < 8; nt++) {
            float p0 = __expf(sacc[nt][0] - nm0);
            float p1 = __expf(sacc[nt][1] - nm0);
            float p2 = __expf(sacc[nt][2] - nm1);
            float p3 = __expf(sacc[nt][3] - nm1);
            sacc[nt][0] = p0; sacc[nt][1] = p1; sacc[nt][2] = p2; sacc[nt][3] = p3;
            rs0 += p0 + p1; rs1 += p2 + p3;
        }
        #pragma unroll
        for (int o = 1; o < 4; o <<= 1) {
            rs0 += __shfl_xor_sync(0xffffffffu, rs0, o);
            rs1 += __shfl_xor_sync(0xffffffffu, rs1, o);
        }
        l0 = l0 * sf0 + rs0;
        l1 = l1 * sf1 + rs1;
        #pragma unroll
        for (int nt = 0; nt < 8; nt++) {
            O[nt][0] *= sf0; O[nt][1] *= sf0;
            O[nt][2] *= sf1; O[nt][3] *= sf1;
        }

        // ---- O += P V ----
        #pragma unroll
        for (int kk = 0; kk < 4; kk++) {
            uint32_t ah[4], al[4];
            split2(sacc[2*kk][0],   sacc[2*kk][1],   ah[0], al[0]);
            split2(sacc[2*kk][2],   sacc[2*kk][3],   ah[1], al[1]);
            split2(sacc[2*kk+1][0], sacc[2*kk+1][1], ah[2], al[2]);
            split2(sacc[2*kk+1][2], sacc[2*kk+1][3], ah[3], al[3]);
            #pragma unroll
            for (int pr = 0; pr < 4; pr++) {
                uint32_t bh[4], bl[4];
                uint32_t vo = (uint32_t)((kk*16 + vlr) * ASTR + pr*8 + vlw) * 4;
                ldm4t(bh, VHb + vo);
                ldm4t(bl, VLb + vo);
                #pragma unroll
                for (int sub = 0; sub < 2; sub++) {
                    int nt = pr * 2 + sub;
                    mma_bf16(O[nt], ah, bh + 2*sub);
                    mma_bf16(O[nt], ah, bl + 2*sub);
                    mma_bf16(O[nt], al, bh + 2*sub);
                }
            }
        }
    }

    // ---- epilogue ----
    float inv0 = 1.0f / l0, inv1 = 1.0f / l1;
    long grow0 = rowbase + rbase + g;
    #pragma unroll
    for (int nt = 0; nt < 8; nt++) {
        int col = qoff + nt * 8 + 2 * c;
        uint32_t hw, lw;
        split2(O[nt][0] * inv0, O[nt][1] * inv0, hw, lw);
        oh[(grow0 * DD + col) >> 1] = hw;
        ol[(grow0 * DD + col) >> 1] = lw;
        split2(O[nt][2] * inv1, O[nt][3] * inv1, hw, lw);
        oh[((grow0 + 8) * DD + col) >> 1] = hw;
        ol[((grow0 + 8) * DD + col) >> 1] = lw;
    }
}

// ---------------------------------------------------------------------------
extern "C" void kernel_launch(void* const* d_in, const int* in_sizes, int n_in,
                              void* d_out, int out_size)
{
    const int*   x    = (const int*)  d_in[0];
    const float* emb  = (const float*)d_in[1];
    const float* pe   = (const float*)d_in[2];
    const float* Wqkv = (const float*)d_in[3];
    const float* Wo   = (const float*)d_in[4];
    const float* bo   = (const float*)d_in[5];
    const float* g1   = (const float*)d_in[6];
    const float* b1   = (const float*)d_in[7];
    const float* g2   = (const float*)d_in[8];
    const float* b2   = (const float*)d_in[9];
    const float* W1   = (const float*)d_in[10];
    const float* bf1  = (const float*)d_in[11];
    const float* W2   = (const float*)d_in[12];
    const float* bf2  = (const float*)d_in[13];
    const float* gf   = (const float*)d_in[14];
    const float* bfp  = (const float*)d_in[15];
    const float* Wout = (const float*)d_in[16];
    const float* bfc  = (const float*)d_in[17];
    float* out = (float*)d_out;

    float *h, *t;
    cudaGetSymbolAddress((void**)&h, g_h);
    cudaGetSymbolAddress((void**)&t, g_t);
    __nv_bfloat16 *hh, *hl, *qh, *ql, *oh, *ol, *fh, *fl, *th, *tl;
    cudaGetSymbolAddress((void**)&hh, g_hh);  cudaGetSymbolAddress((void**)&hl, g_hl);
    cudaGetSymbolAddress((void**)&qh, g_qh);  cudaGetSymbolAddress((void**)&ql, g_ql);
    cudaGetSymbolAddress((void**)&oh, g_oh);  cudaGetSymbolAddress((void**)&ol, g_ol);
    cudaGetSymbolAddress((void**)&fh, g_fh);  cudaGetSymbolAddress((void**)&fl, g_fl);
    cudaGetSymbolAddress((void**)&th, g_th);  cudaGetSymbolAddress((void**)&tl, g_tl);
    __nv_bfloat16 *qkvTh, *qkvTl, *woTh, *woTl, *w1Th, *w1Tl, *w2Th, *w2Tl, *outTh, *outTl;
    cudaGetSymbolAddress((void**)&qkvTh, g_qkvT_h);
    cudaGetSymbolAddress((void**)&qkvTl, g_qkvT_l);
    cudaGetSymbolAddress((void**)&woTh,  g_woT_h);
    cudaGetSymbolAddress((void**)&woTl,  g_woT_l);
    cudaGetSymbolAddress((void**)&w1Th,  g_w1T_h);
    cudaGetSymbolAddress((void**)&w1Tl,  g_w1T_l);
    cudaGetSymbolAddress((void**)&w2Th,  g_w2T_h);
    cudaGetSymbolAddress((void**)&w2Tl,  g_w2T_l);
    cudaGetSymbolAddress((void**)&outTh, g_outT_h);
    cudaGetSymbolAddress((void**)&outTl, g_outT_l);

    cudaFuncSetAttribute(attn_mma, cudaFuncAttributeMaxDynamicSharedMemorySize, ATT_SMEM);
    cudaFuncSetAttribute(gemm_bf16<0,0>, cudaFuncAttributeMaxDynamicSharedMemorySize, GEMM_SMEM);
    cudaFuncSetAttribute(gemm_bf16<0,1>, cudaFuncAttributeMaxDynamicSharedMemorySize, GEMM_SMEM);
    cudaFuncSetAttribute(gemm_bf16<1,1>, cudaFuncAttributeMaxDynamicSharedMemorySize, GEMM_SMEM);

    wprep_k<<<dim3(3*DD/32, DD/32, LL), 256>>>(Wqkv, qkvTh, qkvTl, DD, 3*DD);
    wprep_k<<<dim3(DD/32,   DD/32, LL), 256>>>(Wo,   woTh,  woTl,  DD, DD);
    wprep_k<<<dim3(FF/32,   DD/32, LL), 256>>>(W1,   w1Th,  w1Tl,  DD, FF);
    wprep_k<<<dim3(DD/32,   FF/32, LL), 256>>>(W2,   w2Th,  w2Tl,  FF, DD);
    wprep_k<<<dim3(VV/32,   DD/32, 1 ), 256>>>(Wout, outTh, outTl, DD, VV);

    embed_k<<<ROWS, 128>>>(x, emb, pe, h, (uint32_t*)hh, (uint32_t*)hl);

    for (int l = 0; l < LL; l++) {
        gemm_bf16<0,1><<<dim3(32, 12), 256, GEMM_SMEM>>>(
            hh, hl, qkvTh + (long)l * 3*DD*DD, qkvTl + (long)l * 3*DD*DD,
            nullptr, nullptr, (uint32_t*)qh, (uint32_t*)ql, ROWS, 3*DD, DD);
        attn_mma<<<dim3(SS/128, HH, BB), 256, ATT_SMEM>>>(
            qh, ql, (uint32_t*)oh, (uint32_t*)ol);
        gemm_bf16<0,0><<<dim3(32, 4), 256, GEMM_SMEM>>>(
            oh, ol, woTh + (long)l * DD*DD, woTl + (long)l * DD*DD,
            bo + l * DD, t, nullptr, nullptr, ROWS, DD, DD);
        add_ln_k<<<ROWS, 128>>>(t, h, g1 + l * DD, b1 + l * DD,
                                h, (uint32_t*)hh, (uint32_t*)hl);
        gemm_bf16<1,1><<<dim3(32, 16), 256, GEMM_SMEM>>>(
            hh, hl, w1Th + (long)l * FF*DD, w1Tl + (long)l * FF*DD,
            bf1 + l * FF, nullptr, (uint32_t*)fh, (uint32_t*)fl, ROWS, FF, DD);
        gemm_bf16<0,0><<<dim3(32, 4), 256, GEMM_SMEM>>>(
            fh, fl, w2Th + (long)l * DD*FF, w2Tl + (long)l * DD*FF,
            bf2 + l * DD, t, nullptr, nullptr, ROWS, DD, FF);
        add_ln_k<<<ROWS, 128>>>(t, h, g2 + l * DD, b2 + l * DD,
                                h, (uint32_t*)hh, (uint32_t*)hl);
    }

    add_ln_k<<<ROWS, 128>>>(h, nullptr, gf, bfp, t, (uint32_t*)th, (uint32_t*)tl);
    gemm_bf16<0,0><<<dim3(32, 250), 256, GEMM_SMEM>>>(
        th, tl, outTh, outTl, bfc, out, nullptr, nullptr, ROWS, VV, DD);
}

// round 12
// speedup vs baseline: 1.6484x; 1.0284x over previous
#include <cuda_runtime.h>
#include <cuda_bf16.h>
#include <cstdint>

#define BB 2
#define SS 2048
#define DD 512
#define LL 6
#define HH 8
#define FF 2048
#define VV 32000
#define ROWS (BB*SS)   // 4096

// fp32 residual stream scratch
__device__ float g_h [ROWS * DD];
__device__ float g_t [ROWS * DD];
// packed bf16 hi/lo activation planes
__device__ __align__(16) __nv_bfloat16 g_hh [ROWS * DD],  g_hl [ROWS * DD];
__device__ __align__(16) __nv_bfloat16 g_qh [ROWS * 3*DD], g_ql [ROWS * 3*DD];
__device__ __align__(16) __nv_bfloat16 g_oh [ROWS * DD],  g_ol [ROWS * DD];
__device__ __align__(16) __nv_bfloat16 g_fh [ROWS * FF],  g_fl [ROWS * FF];
__device__ __align__(16) __nv_bfloat16 g_th [ROWS * DD],  g_tl [ROWS * DD];
// pre-transposed bf16-split weights: [N][K] row-major
__device__ __align__(16) __nv_bfloat16 g_qkvT_h[LL * 3*DD * DD], g_qkvT_l[LL * 3*DD * DD];
__device__ __align__(16) __nv_bfloat16 g_woT_h [LL * DD * DD],   g_woT_l [LL * DD * DD];
__device__ __align__(16) __nv_bfloat16 g_w1T_h [LL * FF * DD],   g_w1T_l [LL * FF * DD];
__device__ __align__(16) __nv_bfloat16 g_w2T_h [LL * DD * FF],   g_w2T_l [LL * DD * FF];
__device__ __align__(16) __nv_bfloat16 g_outT_h[VV * DD],        g_outT_l[VV * DD];

extern __shared__ char dynsm[];

// ---------------------------------------------------------------------------
__device__ __forceinline__ uint32_t smem_u32(const void* p) {
    uint32_t a;
    asm("{ .reg .u64 t; cvta.to.shared.u64 t, %1; cvt.u32.u64 %0, t; }"
        : "=r"(a) : "l"(p));
    return a;
}
__device__ __forceinline__ void cpa16(uint32_t s, const void* g) {
    asm volatile("cp.async.cg.shared.global [%0], [%1], 16;" :: "r"(s), "l"(g));
}
__device__ __forceinline__ void split2(float x0, float x1, uint32_t& hw, uint32_t& lw) {
    __nv_bfloat16 h0 = __float2bfloat16(x0), h1 = __float2bfloat16(x1);
    __nv_bfloat16 l0 = __float2bfloat16(x0 - __bfloat162float(h0));
    __nv_bfloat16 l1 = __float2bfloat16(x1 - __bfloat162float(h1));
    __nv_bfloat162 hp(h0, h1), lp(l0, l1);
    hw = *(uint32_t*)&hp;
    lw = *(uint32_t*)&lp;
}
__device__ __forceinline__ void mma_bf16(float* d, const uint32_t* a, const uint32_t* b) {
    asm volatile("mma.sync.aligned.m16n8k16.row.col.f32.bf16.bf16.f32 "
        "{%0,%1,%2,%3}, {%4,%5,%6,%7}, {%8,%9}, {%0,%1,%2,%3};"
        : "+f"(d[0]), "+f"(d[1]), "+f"(d[2]), "+f"(d[3])
        : "r"(a[0]), "r"(a[1]), "r"(a[2]), "r"(a[3]), "r"(b[0]), "r"(b[1]));
}
__device__ __forceinline__ void ldm4(uint32_t* r, uint32_t a) {
    asm volatile("ldmatrix.sync.aligned.m8n8.x4.shared.b16 {%0,%1,%2,%3}, [%4];"
        : "=r"(r[0]), "=r"(r[1]), "=r"(r[2]), "=r"(r[3]) : "r"(a));
}
__device__ __forceinline__ void ldm4t(uint32_t* r, uint32_t a) {
    asm volatile("ldmatrix.sync.aligned.m8n8.x4.trans.shared.b16 {%0,%1,%2,%3}, [%4];"
        : "=r"(r[0]), "=r"(r[1]), "=r"(r[2]), "=r"(r[3]) : "r"(a));
}

// ---------------------------------------------------------------------------
// Weight prep: W[K,N] fp32 -> WT hi/lo [N,K] bf16
// ---------------------------------------------------------------------------
__global__ void wprep_k(const float* __restrict__ W, __nv_bfloat16* __restrict__ hi,
                        __nv_bfloat16* __restrict__ lo, int K, int N)
{
    __shared__ float ts[32][33];
    long moff = (long)blockIdx.z * K * N;
    int kb = blockIdx.y * 32, nb = blockIdx.x * 32;
    int r = threadIdx.x >> 5, c = threadIdx.x & 31;
    #pragma unroll
    for (int i = 0; i < 4; i++)
        ts[r + i*8][c] = W[moff + (long)(kb + r + i*8) * N + nb + c];
    __syncthreads();
    #pragma unroll
    for (int i = 0; i < 4; i++) {
        int n = r + i*8;
        float x = ts[c][n];
        __nv_bfloat16 h = __float2bfloat16(x);
        __nv_bfloat16 l = __float2bfloat16(x - __bfloat162float(h));
        long oidx = moff + (long)(nb + n) * K + kb + c;
        hi[oidx] = h;
        lo[oidx] = l;
    }
}

// ---------------------------------------------------------------------------
// Embedding + PE -> fp32 h + hi/lo planes
// ---------------------------------------------------------------------------
__global__ void embed_k(const int* __restrict__ x, const float* __restrict__ emb,
                        const float* __restrict__ pe, float* __restrict__ h,
                        uint32_t* __restrict__ oh, uint32_t* __restrict__ ol)
{
    int row = blockIdx.x, tid = threadIdx.x;
    int s   = row & (SS - 1);
    int tok = x[row];
    float4 ev = ((const float4*)(emb + (long)tok * DD))[tid];
    float4 pv = ((const float4*)(pe  + (long)s   * DD))[tid];
    float4 o;
    o.x = ev.x + pv.x; o.y = ev.y + pv.y; o.z = ev.z + pv.z; o.w = ev.w + pv.w;
    ((float4*)(h + (long)row * DD))[tid] = o;
    uint32_t hw, lw;
    int wi = row * (DD/2) + tid * 2;
    split2(o.x, o.y, hw, lw); oh[wi] = hw;   ol[wi] = lw;
    split2(o.z, o.w, hw, lw); oh[wi+1] = hw; ol[wi+1] = lw;
}

// ---------------------------------------------------------------------------
// out = LayerNorm(x (+ res)) * g + b -> fp32 + hi/lo planes
// ---------------------------------------------------------------------------
__global__ void add_ln_k(const float* __restrict__ x, const float* __restrict__ res,
                         const float* __restrict__ gg, const float* __restrict__ bb,
                         float* __restrict__ outF,
                         uint32_t* __restrict__ outH, uint32_t* __restrict__ outL)
{
    int row = blockIdx.x, tid = threadIdx.x;
    float4 v = ((const float4*)(x + (long)row * DD))[tid];
    if (res) {
        float4 rv = ((const float4*)(res + (long)row * DD))[tid];
        v.x += rv.x; v.y += rv.y; v.z += rv.z; v.w += rv.w;
    }
    float s  = v.x + v.y + v.z + v.w;
    float s2 = v.x*v.x + v.y*v.y + v.z*v.z + v.w*v.w;
    #pragma unroll
    for (int o = 16; o; o >>= 1) {
        s  += __shfl_xor_sync(0xffffffffu, s,  o);
        s2 += __shfl_xor_sync(0xffffffffu, s2, o);
    }
    __shared__ float ssum[4], ssq[4];
    int wid = tid >> 5;
    if ((tid & 31) == 0) { ssum[wid] = s; ssq[wid] = s2; }
    __syncthreads();
    s  = ssum[0] + ssum[1] + ssum[2] + ssum[3];
    s2 = ssq[0]  + ssq[1]  + ssq[2]  + ssq[3];
    float mean = s * (1.0f / DD);
    float var  = s2 * (1.0f / DD) - mean * mean;
    float inv  = rsqrtf(var + 1e-5f);
    float4 gv = ((const float4*)gg)[tid];
    float4 bv = ((const float4*)bb)[tid];
    float4 o;
    o.x = (v.x - mean) * inv * gv.x + bv.x;
    o.y = (v.y - mean) * inv * gv.y + bv.y;
    o.z = (v.z - mean) * inv * gv.z + bv.z;
    o.w = (v.w - mean) * inv * gv.w + bv.w;
    ((float4*)(outF + (long)row * DD))[tid] = o;
    uint32_t hw, lw;
    int wi = row * (DD/2) + tid * 2;
    split2(o.x, o.y, hw, lw); outH[wi] = hw;   outL[wi] = lw;
    split2(o.z, o.w, hw, lw); outH[wi+1] = hw; outL[wi+1] = lw;
}

// ---------------------------------------------------------------------------
// bf16 3-term tensor GEMM: 256 threads, 64x32 warp tile, BK=32,
// 2 buffers / 80KB smem, ONE __syncthreads per K-tile (prefetch dist 1).
// ---------------------------------------------------------------------------
#define GSTR 20
#define GPL  (128*GSTR)
#define GEMM_SMEM (8*GPL*4)        // 81920 B

template<int RELU, int OUTMODE>
__global__ __launch_bounds__(256)
void gemm_bf16(const __nv_bfloat16* __restrict__ Ahp, const __nv_bfloat16* __restrict__ Alp,
               const __nv_bfloat16* __restrict__ Bhp, const __nv_bfloat16* __restrict__ Blp,
               const float* __restrict__ bias,
               float* __restrict__ C, uint32_t* __restrict__ Chw, uint32_t* __restrict__ Clw,
               int M, int N, int K)
{
    uint32_t* sm = (uint32_t*)dynsm;
    const int tid = threadIdx.x, warp = tid >> 5, lane = tid & 31;
    const int g = lane >> 2, c = lane & 3;
    const int bm = blockIdx.x * 128, bn = blockIdx.y * 128;
    const int wm = (warp >> 2) * 64, wn = (warp & 3) * 32;
    const uint32_t sb = smem_u32(sm);
    const int T = K / 32;

    const int alr = lane & 15, alw = (lane >> 4) * 4;
    const int blr = (lane & 7) + ((lane >> 4) << 3);
    const int blw = ((lane >> 3) & 1) * 4;

    auto stage = [&](int t, int b) {
        #pragma unroll
        for (int i = 0; i < 2; i++) {
            int id = tid + 256 * i, row = id >> 2, cc = id & 3;
            uint32_t doff = (uint32_t)(row * GSTR + cc * 4) * 4;
            uint32_t dbase = sb + (uint32_t)(b * 4 * GPL) * 4 + doff;
            long asrc = (long)(bm + row) * K + t * 32 + cc * 8;
            long bsrc = (long)(bn + row) * K + t * 32 + cc * 8;
            cpa16(dbase,             Ahp + asrc);
            cpa16(dbase + GPL*4,     Alp + asrc);
            cpa16(dbase + 2*GPL*4,   Bhp + bsrc);
            cpa16(dbase + 3*GPL*4,   Blp + bsrc);
        }
        asm volatile("cp.async.commit_group;");
    };

    float acc[4][4][4] = {};

    stage(0, 0);

    for (int t = 0; t < T; t++) {
        asm volatile("cp.async.wait_group 0;");
        __syncthreads();
        // buffer (t+1)&1 was last consumed at iteration t-1; the sync above
        // proves all warps finished it -> safe to refill while computing t.
        if (t + 1 < T) stage(t + 1, (t + 1) & 1);

        const uint32_t bufb = sb + (uint32_t)((t & 1) * 4 * GPL) * 4;

        #pragma unroll
        for (int kk = 0; kk < 2; kk++) {
            uint32_t ah[4][4], al[4][4];
            #pragma unroll
            for (int mt = 0; mt < 4; mt++) {
                uint32_t ao = (uint32_t)((wm + mt*16 + alr) * GSTR + kk*8 + alw) * 4;
                ldm4(ah[mt], bufb + ao);
                ldm4(al[mt], bufb + GPL*4 + ao);
            }
            #pragma unroll
            for (int pr = 0; pr < 2; pr++) {
                uint32_t bh[4], bl[4];
                uint32_t bo = (uint32_t)((wn + pr*16 + blr) * GSTR + kk*8 + blw) * 4;
                ldm4(bh, bufb + 2*GPL*4 + bo);
                ldm4(bl, bufb + 3*GPL*4 + bo);
                #pragma unroll
                for (int sub = 0; sub < 2; sub++) {
                    int nt = pr * 2 + sub;
                    #pragma unroll
                    for (int mt = 0; mt < 4; mt++) {
                        mma_bf16(acc[mt][nt], ah[mt], bh + 2*sub);
                        mma_bf16(acc[mt][nt], ah[mt], bl + 2*sub);
                        mma_bf16(acc[mt][nt], al[mt], bh + 2*sub);
                    }
                }
            }
        }
    }

    #pragma unroll
    for (int mt = 0; mt < 4; mt++) {
        #pragma unroll
        for (int nt = 0; nt < 4; nt++) {
            int col = bn + wn + nt*8 + 2*c;
            float bx = 0.f, by = 0.f;
            if (bias) { bx = bias[col]; by = bias[col + 1]; }
            long r0 = bm + wm + mt*16 + g;
            float v0 = acc[mt][nt][0] + bx, v1 = acc[mt][nt][1] + by;
            float v2 = acc[mt][nt][2] + bx, v3 = acc[mt][nt][3] + by;
            if (RELU) {
                v0 = fmaxf(v0, 0.f); v1 = fmaxf(v1, 0.f);
                v2 = fmaxf(v2, 0.f); v3 = fmaxf(v3, 0.f);
            }
            if (OUTMODE == 0) {
                *(float2*)(C + r0 * N + col)       = make_float2(v0, v1);
                *(float2*)(C + (r0 + 8) * N + col) = make_float2(v2, v3);
            } else {
                uint32_t hw, lw;
                split2(v0, v1, hw, lw);
                Chw[(r0 * N + col) >> 1] = hw; Clw[(r0 * N + col) >> 1] = lw;
                split2(v2, v3, hw, lw);
                Chw[((r0 + 8) * N + col) >> 1] = hw; Clw[((r0 + 8) * N + col) >> 1] = lw;
            }
        }
    }
}

// ---------------------------------------------------------------------------
// mma flash attention (round-8 known-good version, single-buffered K/V).
// CTA = 128 q-rows x (head, batch), 8 warps x 16 rows.
// ---------------------------------------------------------------------------
#define ASTR 36
#define AQH 0
#define AQL (128*ASTR)
#define AKH (2*128*ASTR)
#define AKL (AKH + 64*ASTR)
#define AVH (AKH + 2*64*ASTR)
#define AVL (AKH + 3*64*ASTR)
#define ATT_SMEM ((2*128*ASTR + 4*64*ASTR)*4)   // 73728 B

__global__ __launch_bounds__(256)
void attn_mma(const __nv_bfloat16* __restrict__ qh, const __nv_bfloat16* __restrict__ ql,
              uint32_t* __restrict__ oh, uint32_t* __restrict__ ol)
{
    uint32_t* sm = (uint32_t*)dynsm;
    const uint32_t sb = smem_u32(sm);
    const int tid = threadIdx.x, warp = tid >> 5, lane = tid & 31;
    const int g = lane >> 2, c = lane & 3;
    const int qt = (int)gridDim.x - 1 - (int)blockIdx.x;
    const int h = blockIdx.y, b = blockIdx.z;
    const long rowbase = (long)b * SS;
    const int qoff = h << 6;

    const int alr = lane & 15, alw = (lane >> 4) * 4;
    const int blr = (lane & 7) + ((lane >> 4) << 3);
    const int blw = ((lane >> 3) & 1) * 4;
    const int vlr = ((lane >> 3) & 1) * 8 + (lane & 7);
    const int vlw = (lane >> 4) * 4;

    // stage Q (128 rows x 64, hi+lo)
    #pragma unroll
    for (int p = 0; p < 2; p++) {
        const __nv_bfloat16* src = p ? ql : qh;
        uint32_t dst = sb + (p ? AQL : AQH) * 4;
        #pragma unroll
        for (int i = 0; i < 4; i++) {
            int id = tid + 256 * i;
            int row = id >> 3, ch = id & 7;
            cpa16(dst + (uint32_t)(row * ASTR + ch * 4) * 4,
                  src + (rowbase + qt * 128 + row) * 1536 + qoff + ch * 8);
        }
    }
    asm volatile("cp.async.commit_group;");
    asm volatile("cp.async.wait_group 0;");
    __syncthreads();

    // hoist Q fragments (4 k-chunks x hi/lo)
    uint32_t Qh[4][4], Ql[4][4];
    #pragma unroll
    for (int kk = 0; kk < 4; kk++) {
        uint32_t qo = (uint32_t)((warp*16 + alr) * ASTR + kk*8 + alw) * 4;
        ldm4(Qh[kk], sb + AQH*4 + qo);
        ldm4(Ql[kk], sb + AQL*4 + qo);
    }

    float m0 = -1e30f, m1 = -1e30f, l0 = 0.f, l1 = 0.f;
    float O[8][4] = {};
    const int nk = 2 * qt + 2;
    const int rbase = qt * 128 + warp * 16;

    for (int kt = 0; kt < nk; kt++) {
        // stage K and V rows (hi+lo) via cp.async
        #pragma unroll
        for (int i = 0; i < 8; i++) {
            int id = tid + 256 * i;
            int p  = (id >> 9) & 1;
            int kv = id >> 10;
            int rem = id & 511;
            int row = rem >> 3, ch = rem & 7;
            const __nv_bfloat16* src = p ? ql : qh;
            uint32_t base = kv ? (p ? AVL : AVH) : (p ? AKL : AKH);
            cpa16(sb + (uint32_t)(base + row * ASTR + ch * 4) * 4,
                  src + (rowbase + kt * 64 + row) * 1536 + (kv ? 1024 : 512) + qoff + ch * 8);
        }
        asm volatile("cp.async.commit_group;");
        asm volatile("cp.async.wait_group 0;");
        __syncthreads();

        // ---- S = Q K^T ----
        float sacc[8][4] = {};
        #pragma unroll
        for (int kk = 0; kk < 4; kk++) {
            #pragma unroll
            for (int pr = 0; pr < 4; pr++) {
                uint32_t bh[4], bl[4];
                uint32_t bo = (uint32_t)((pr*16 + blr) * ASTR + kk*8 + blw) * 4;
                ldm4(bh, sb + AKH*4 + bo);
                ldm4(bl, sb + AKL*4 + bo);
                #pragma unroll
                for (int sub = 0; sub < 2; sub++) {
                    int nt = pr * 2 + sub;
                    mma_bf16(sacc[nt], Qh[kk], bh + 2*sub);
                    mma_bf16(sacc[nt], Qh[kk], bl + 2*sub);
                    mma_bf16(sacc[nt], Ql[kk], bh + 2*sub);
                }
            }
        }

        // ---- mask + online softmax ----
        const float scale = 0.125f;
        const bool diag = (kt >= 2 * qt);
        const int row0 = rbase + g, row1 = rbase + g + 8;
        const int colb = kt * 64 + 2 * c;
        float rm0 = -1e30f, rm1 = -1e30f;
        #pragma unroll
        for (int nt = 0; nt < 8; nt++) {
            int c0 = colb + nt * 8;
            float v0 = sacc[nt][0] * scale, v1 = sacc[nt][1] * scale;
            float v2 = sacc[nt][2] * scale, v3 = sacc[nt][3] * scale;
            if (diag) {
                if (c0     > row0) v0 = -1e30f;
                if (c0 + 1 > row0) v1 = -1e30f;
                if (c0     > row1) v2 = -1e30f;
                if (c0 + 1 > row1) v3 = -1e30f;
            }
            sacc[nt][0] = v0; sacc[nt][1] = v1; sacc[nt][2] = v2; sacc[nt][3] = v3;
            rm0 = fmaxf(rm0, fmaxf(v0, v1));
            rm1 = fmaxf(rm1, fmaxf(v2, v3));
        }
        #pragma unroll
        for (int o = 1; o < 4; o <<= 1) {
            rm0 = fmaxf(rm0, __shfl_xor_sync(0xffffffffu, rm0, o));
            rm1 = fmaxf(rm1, __shfl_xor_sync(0xffffffffu, rm1, o));
        }
        float nm0 = fmaxf(m0, rm0), nm1 = fmaxf(m1, rm1);
        float sf0 = __expf(m0 - nm0), sf1 = __expf(m1 - nm1);
        m0 = nm0; m1 = nm1;
        float rs0 = 0.f, rs1 = 0.f;
        #pragma unroll
        for (int nt = 0; nt < 8; nt++) {
            float p0 = __expf(sacc[nt][0] - nm0);
            float p1 = __expf(sacc[nt][1] - nm0);
            float p2 = __expf(sacc[nt][2] - nm1);
            float p3 = __expf(sacc[nt][3] - nm1);
            sacc[nt][0] = p0; sacc[nt][1] = p1; sacc[nt][2] = p2; sacc[nt][3] = p3;
            rs0 += p0 + p1; rs1 += p2 + p3;
        }
        #pragma unroll
        for (int o = 1; o < 4; o <<= 1) {
            rs0 += __shfl_xor_sync(0xffffffffu, rs0, o);
            rs1 += __shfl_xor_sync(0xffffffffu, rs1, o);
        }
        l0 = l0 * sf0 + rs0;
        l1 = l1 * sf1 + rs1;
        #pragma unroll
        for (int nt = 0; nt < 8; nt++) {
            O[nt][0] *= sf0; O[nt][1] *= sf0;
            O[nt][2] *= sf1; O[nt][3] *= sf1;
        }

        // ---- O += P V ----
        #pragma unroll
        for (int kk = 0; kk < 4; kk++) {
            uint32_t ah[4], al[4];
            split2(sacc[2*kk][0],   sacc[2*kk][1],   ah[0], al[0]);
            split2(sacc[2*kk][2],   sacc[2*kk][3],   ah[1], al[1]);
            split2(sacc[2*kk+1][0], sacc[2*kk+1][1], ah[2], al[2]);
            split2(sacc[2*kk+1][2], sacc[2*kk+1][3], ah[3], al[3]);
            #pragma unroll
            for (int pr = 0; pr < 4; pr++) {
                uint32_t bh[4], bl[4];
                uint32_t vo = (uint32_t)((kk*16 + vlr) * ASTR + pr*8 + vlw) * 4;
                ldm4t(bh, sb + AVH*4 + vo);
                ldm4t(bl, sb + AVL*4 + vo);
                #pragma unroll
                for (int sub = 0; sub < 2; sub++) {
                    int nt = pr * 2 + sub;
                    mma_bf16(O[nt], ah, bh + 2*sub);
                    mma_bf16(O[nt], ah, bl + 2*sub);
                    mma_bf16(O[nt], al, bh + 2*sub);
                }
            }
        }
        __syncthreads();
    }

    // ---- epilogue ----
    float inv0 = 1.0f / l0, inv1 = 1.0f / l1;
    long grow0 = rowbase + rbase + g;
    #pragma unroll
    for (int nt = 0; nt < 8; nt++) {
        int col = qoff + nt * 8 + 2 * c;
        uint32_t hw, lw;
        split2(O[nt][0] * inv0, O[nt][1] * inv0, hw, lw);
        oh[(grow0 * DD + col) >> 1] = hw;
        ol[(grow0 * DD + col) >> 1] = lw;
        split2(O[nt][2] * inv1, O[nt][3] * inv1, hw, lw);
        oh[((grow0 + 8) * DD + col) >> 1] = hw;
        ol[((grow0 + 8) * DD + col) >> 1] = lw;
    }
}

// ---------------------------------------------------------------------------
extern "C" void kernel_launch(void* const* d_in, const int* in_sizes, int n_in,
                              void* d_out, int out_size)
{
    const int*   x    = (const int*)  d_in[0];
    const float* emb  = (const float*)d_in[1];
    const float* pe   = (const float*)d_in[2];
    const float* Wqkv = (const float*)d_in[3];
    const float* Wo   = (const float*)d_in[4];
    const float* bo   = (const float*)d_in[5];
    const float* g1   = (const float*)d_in[6];
    const float* b1   = (const float*)d_in[7];
    const float* g2   = (const float*)d_in[8];
    const float* b2   = (const float*)d_in[9];
    const float* W1   = (const float*)d_in[10];
    const float* bf1  = (const float*)d_in[11];
    const float* W2   = (const float*)d_in[12];
    const float* bf2  = (const float*)d_in[13];
    const float* gf   = (const float*)d_in[14];
    const float* bfp  = (const float*)d_in[15];
    const float* Wout = (const float*)d_in[16];
    const float* bfc  = (const float*)d_in[17];
    float* out = (float*)d_out;

    float *h, *t;
    cudaGetSymbolAddress((void**)&h, g_h);
    cudaGetSymbolAddress((void**)&t, g_t);
    __nv_bfloat16 *hh, *hl, *qh, *ql, *oh, *ol, *fh, *fl, *th, *tl;
    cudaGetSymbolAddress((void**)&hh, g_hh);  cudaGetSymbolAddress((void**)&hl, g_hl);
    cudaGetSymbolAddress((void**)&qh, g_qh);  cudaGetSymbolAddress((void**)&ql, g_ql);
    cudaGetSymbolAddress((void**)&oh, g_oh);  cudaGetSymbolAddress((void**)&ol, g_ol);
    cudaGetSymbolAddress((void**)&fh, g_fh);  cudaGetSymbolAddress((void**)&fl, g_fl);
    cudaGetSymbolAddress((void**)&th, g_th);  cudaGetSymbolAddress((void**)&tl, g_tl);
    __nv_bfloat16 *qkvTh, *qkvTl, *woTh, *woTl, *w1Th, *w1Tl, *w2Th, *w2Tl, *outTh, *outTl;
    cudaGetSymbolAddress((void**)&qkvTh, g_qkvT_h);
    cudaGetSymbolAddress((void**)&qkvTl, g_qkvT_l);
    cudaGetSymbolAddress((void**)&woTh,  g_woT_h);
    cudaGetSymbolAddress((void**)&woTl,  g_woT_l);
    cudaGetSymbolAddress((void**)&w1Th,  g_w1T_h);
    cudaGetSymbolAddress((void**)&w1Tl,  g_w1T_l);
    cudaGetSymbolAddress((void**)&w2Th,  g_w2T_h);
    cudaGetSymbolAddress((void**)&w2Tl,  g_w2T_l);
    cudaGetSymbolAddress((void**)&outTh, g_outT_h);
    cudaGetSymbolAddress((void**)&outTl, g_outT_l);

    cudaFuncSetAttribute(attn_mma, cudaFuncAttributeMaxDynamicSharedMemorySize, ATT_SMEM);
    cudaFuncSetAttribute(gemm_bf16<0,0>, cudaFuncAttributeMaxDynamicSharedMemorySize, GEMM_SMEM);
    cudaFuncSetAttribute(gemm_bf16<0,1>, cudaFuncAttributeMaxDynamicSharedMemorySize, GEMM_SMEM);
    cudaFuncSetAttribute(gemm_bf16<1,1>, cudaFuncAttributeMaxDynamicSharedMemorySize, GEMM_SMEM);

    wprep_k<<<dim3(3*DD/32, DD/32, LL), 256>>>(Wqkv, qkvTh, qkvTl, DD, 3*DD);
    wprep_k<<<dim3(DD/32,   DD/32, LL), 256>>>(Wo,   woTh,  woTl,  DD, DD);
    wprep_k<<<dim3(FF/32,   DD/32, LL), 256>>>(W1,   w1Th,  w1Tl,  DD, FF);
    wprep_k<<<dim3(DD/32,   FF/32, LL), 256>>>(W2,   w2Th,  w2Tl,  FF, DD);
    wprep_k<<<dim3(VV/32,   DD/32, 1 ), 256>>>(Wout, outTh, outTl, DD, VV);

    embed_k<<<ROWS, 128>>>(x, emb, pe, h, (uint32_t*)hh, (uint32_t*)hl);

    for (int l = 0; l < LL; l++) {
        gemm_bf16<0,1><<<dim3(32, 12), 256, GEMM_SMEM>>>(
            hh, hl, qkvTh + (long)l * 3*DD*DD, qkvTl + (long)l * 3*DD*DD,
            nullptr, nullptr, (uint32_t*)qh, (uint32_t*)ql, ROWS, 3*DD, DD);
        attn_mma<<<dim3(SS/128, HH, BB), 256, ATT_SMEM>>>(
            qh, ql, (uint32_t*)oh, (uint32_t*)ol);
        gemm_bf16<0,0><<<dim3(32, 4), 256, GEMM_SMEM>>>(
            oh, ol, woTh + (long)l * DD*DD, woTl + (long)l * DD*DD,
            bo + l * DD, t, nullptr, nullptr, ROWS, DD, DD);
        add_ln_k<<<ROWS, 128>>>(t, h, g1 + l * DD, b1 + l * DD,
                                h, (uint32_t*)hh, (uint32_t*)hl);
        gemm_bf16<1,1><<<dim3(32, 16), 256, GEMM_SMEM>>>(
            hh, hl, w1Th + (long)l * FF*DD, w1Tl + (long)l * FF*DD,
            bf1 + l * FF, nullptr, (uint32_t*)fh, (uint32_t*)fl, ROWS, FF, DD);
        gemm_bf16<0,0><<<dim3(32, 4), 256, GEMM_SMEM>>>(
            fh, fl, w2Th + (long)l * DD*FF, w2Tl + (long)l * DD*FF,
            bf2 + l * DD, t, nullptr, nullptr, ROWS, DD, FF);
        add_ln_k<<<ROWS, 128>>>(t, h, g2 + l * DD, b2 + l * DD,
                                h, (uint32_t*)hh, (uint32_t*)hl);
    }

    add_ln_k<<<ROWS, 128>>>(h, nullptr, gf, bfp, t, (uint32_t*)th, (uint32_t*)tl);
    gemm_bf16<0,0><<<dim3(32, 250), 256, GEMM_SMEM>>>(
        th, tl, outTh, outTl, bfc, out, nullptr, nullptr, ROWS, VV, DD);
}

// round 13
// speedup vs baseline: 1.9003x; 1.1528x over previous
#include <cuda_runtime.h>
#include <cuda_bf16.h>
#include <cuda_fp16.h>
#include <cstdint>

#define BB 2
#define SS 2048
#define DD 512
#define LL 6
#define HH 8
#define FF 2048
#define VV 32000
#define ROWS (BB*SS)   // 4096

// fp32 residual stream scratch
__device__ float g_h [ROWS * DD];
__device__ float g_t [ROWS * DD];
// packed bf16 hi/lo activation planes
__device__ __align__(16) __nv_bfloat16 g_hh [ROWS * DD],  g_hl [ROWS * DD];
__device__ __align__(16) __nv_bfloat16 g_qh [ROWS * 3*DD], g_ql [ROWS * 3*DD];
__device__ __align__(16) __nv_bfloat16 g_oh [ROWS * DD],  g_ol [ROWS * DD];
__device__ __align__(16) __nv_bfloat16 g_fh [ROWS * FF],  g_fl [ROWS * FF];
// fp16 single plane for final LN output
__device__ __align__(16) __half g_tf [ROWS * DD];
// pre-transposed bf16-split weights: [N][K] row-major
__device__ __align__(16) __nv_bfloat16 g_qkvT_h[LL * 3*DD * DD], g_qkvT_l[LL * 3*DD * DD];
__device__ __align__(16) __nv_bfloat16 g_woT_h [LL * DD * DD],   g_woT_l [LL * DD * DD];
__device__ __align__(16) __nv_bfloat16 g_w1T_h [LL * FF * DD],   g_w1T_l [LL * FF * DD];
__device__ __align__(16) __nv_bfloat16 g_w2T_h [LL * DD * FF],   g_w2T_l [LL * DD * FF];
// fp16 single-plane transposed Wout
__device__ __align__(16) __half g_outT_f[VV * DD];

extern __shared__ char dynsm[];

// ---------------------------------------------------------------------------
__device__ __forceinline__ uint32_t smem_u32(const void* p) {
    uint32_t a;
    asm("{ .reg .u64 t; cvta.to.shared.u64 t, %1; cvt.u32.u64 %0, t; }"
        : "=r"(a) : "l"(p));
    return a;
}
__device__ __forceinline__ void cpa16(uint32_t s, const void* g) {
    asm volatile("cp.async.cg.shared.global [%0], [%1], 16;" :: "r"(s), "l"(g));
}
__device__ __forceinline__ void split2(float x0, float x1, uint32_t& hw, uint32_t& lw) {
    __nv_bfloat16 h0 = __float2bfloat16(x0), h1 = __float2bfloat16(x1);
    __nv_bfloat16 l0 = __float2bfloat16(x0 - __bfloat162float(h0));
    __nv_bfloat16 l1 = __float2bfloat16(x1 - __bfloat162float(h1));
    __nv_bfloat162 hp(h0, h1), lp(l0, l1);
    hw = *(uint32_t*)&hp;
    lw = *(uint32_t*)&lp;
}
__device__ __forceinline__ void mma_bf16(float* d, const uint32_t* a, const uint32_t* b) {
    asm volatile("mma.sync.aligned.m16n8k16.row.col.f32.bf16.bf16.f32 "
        "{%0,%1,%2,%3}, {%4,%5,%6,%7}, {%8,%9}, {%0,%1,%2,%3};"
        : "+f"(d[0]), "+f"(d[1]), "+f"(d[2]), "+f"(d[3])
        : "r"(a[0]), "r"(a[1]), "r"(a[2]), "r"(a[3]), "r"(b[0]), "r"(b[1]));
}
__device__ __forceinline__ void mma_f16(float* d, const uint32_t* a, const uint32_t* b) {
    asm volatile("mma.sync.aligned.m16n8k16.row.col.f32.f16.f16.f32 "
        "{%0,%1,%2,%3}, {%4,%5,%6,%7}, {%8,%9}, {%0,%1,%2,%3};"
        : "+f"(d[0]), "+f"(d[1]), "+f"(d[2]), "+f"(d[3])
        : "r"(a[0]), "r"(a[1]), "r"(a[2]), "r"(a[3]), "r"(b[0]), "r"(b[1]));
}
__device__ __forceinline__ void ldm4(uint32_t* r, uint32_t a) {
    asm volatile("ldmatrix.sync.aligned.m8n8.x4.shared.b16 {%0,%1,%2,%3}, [%4];"
        : "=r"(r[0]), "=r"(r[1]), "=r"(r[2]), "=r"(r[3]) : "r"(a));
}
__device__ __forceinline__ void ldm4t(uint32_t* r, uint32_t a) {
    asm volatile("ldmatrix.sync.aligned.m8n8.x4.trans.shared.b16 {%0,%1,%2,%3}, [%4];"
        : "=r"(r[0]), "=r"(r[1]), "=r"(r[2]), "=r"(r[3]) : "r"(a));
}

// ---------------------------------------------------------------------------
// Weight prep: W[K,N] fp32 -> WT hi/lo [N,K] bf16
// ---------------------------------------------------------------------------
__global__ void wprep_k(const float* __restrict__ W, __nv_bfloat16* __restrict__ hi,
                        __nv_bfloat16* __restrict__ lo, int K, int N)
{
    __shared__ float ts[32][33];
    long moff = (long)blockIdx.z * K * N;
    int kb = blockIdx.y * 32, nb = blockIdx.x * 32;
    int r = threadIdx.x >> 5, c = threadIdx.x & 31;
    #pragma unroll
    for (int i = 0; i < 4; i++)
        ts[r + i*8][c] = W[moff + (long)(kb + r + i*8) * N + nb + c];
    __syncthreads();
    #pragma unroll
    for (int i = 0; i < 4; i++) {
        int n = r + i*8;
        float x = ts[c][n];
        __nv_bfloat16 h = __float2bfloat16(x);
        __nv_bfloat16 l = __float2bfloat16(x - __bfloat162float(h));
        long oidx = moff + (long)(nb + n) * K + kb + c;
        hi[oidx] = h;
        lo[oidx] = l;
    }
}

// Weight prep fp16 single plane: W[K,N] fp32 -> WT [N,K] fp16
__global__ void wprep16_k(const float* __restrict__ W, __half* __restrict__ o,
                          int K, int N)
{
    __shared__ float ts[32][33];
    int kb = blockIdx.y * 32, nb = blockIdx.x * 32;
    int r = threadIdx.x >> 5, c = threadIdx.x & 31;
    #pragma unroll
    for (int i = 0; i < 4; i++)
        ts[r + i*8][c] = W[(long)(kb + r + i*8) * N + nb + c];
    __syncthreads();
    #pragma unroll
    for (int i = 0; i < 4; i++) {
        int n = r + i*8;
        o[(long)(nb + n) * K + kb + c] = __float2half_rn(ts[c][n]);
    }
}

// ---------------------------------------------------------------------------
// Embedding + PE -> fp32 h + hi/lo planes
// ---------------------------------------------------------------------------
__global__ void embed_k(const int* __restrict__ x, const float* __restrict__ emb,
                        const float* __restrict__ pe, float* __restrict__ h,
                        uint32_t* __restrict__ oh, uint32_t* __restrict__ ol)
{
    int row = blockIdx.x, tid = threadIdx.x;
    int s   = row & (SS - 1);
    int tok = x[row];
    float4 ev = ((const float4*)(emb + (long)tok * DD))[tid];
    float4 pv = ((const float4*)(pe  + (long)s   * DD))[tid];
    float4 o;
    o.x = ev.x + pv.x; o.y = ev.y + pv.y; o.z = ev.z + pv.z; o.w = ev.w + pv.w;
    ((float4*)(h + (long)row * DD))[tid] = o;
    uint32_t hw, lw;
    int wi = row * (DD/2) + tid * 2;
    split2(o.x, o.y, hw, lw); oh[wi] = hw;   ol[wi] = lw;
    split2(o.z, o.w, hw, lw); oh[wi+1] = hw; ol[wi+1] = lw;
}

// ---------------------------------------------------------------------------
// out = LayerNorm(x (+ res)) * g + b.
// MODE 0: fp32 + bf16 hi/lo planes.  MODE 1: fp32 + packed fp16 plane (outH).
// ---------------------------------------------------------------------------
template<int MODE>
__global__ void add_ln_k(const float* __restrict__ x, const float* __restrict__ res,
                         const float* __restrict__ gg, const float* __restrict__ bb,
                         float* __restrict__ outF,
                         uint32_t* __restrict__ outH, uint32_t* __restrict__ outL)
{
    int row = blockIdx.x, tid = threadIdx.x;
    float4 v = ((const float4*)(x + (long)row * DD))[tid];
    if (res) {
        float4 rv = ((const float4*)(res + (long)row * DD))[tid];
        v.x += rv.x; v.y += rv.y; v.z += rv.z; v.w += rv.w;
    }
    float s  = v.x + v.y + v.z + v.w;
    float s2 = v.x*v.x + v.y*v.y + v.z*v.z + v.w*v.w;
    #pragma unroll
    for (int o = 16; o; o >>= 1) {
        s  += __shfl_xor_sync(0xffffffffu, s,  o);
        s2 += __shfl_xor_sync(0xffffffffu, s2, o);
    }
    __shared__ float ssum[4], ssq[4];
    int wid = tid >> 5;
    if ((tid & 31) == 0) { ssum[wid] = s; ssq[wid] = s2; }
    __syncthreads();
    s  = ssum[0] + ssum[1] + ssum[2] + ssum[3];
    s2 = ssq[0]  + ssq[1]  + ssq[2]  + ssq[3];
    float mean = s * (1.0f / DD);
    float var  = s2 * (1.0f / DD) - mean * mean;
    float inv  = rsqrtf(var + 1e-5f);
    float4 gv = ((const float4*)gg)[tid];
    float4 bv = ((const float4*)bb)[tid];
    float4 o;
    o.x = (v.x - mean) * inv * gv.x + bv.x;
    o.y = (v.y - mean) * inv * gv.y + bv.y;
    o.z = (v.z - mean) * inv * gv.z + bv.z;
    o.w = (v.w - mean) * inv * gv.w + bv.w;
    ((float4*)(outF + (long)row * DD))[tid] = o;
    int wi = row * (DD/2) + tid * 2;
    if (MODE == 0) {
        uint32_t hw, lw;
        split2(o.x, o.y, hw, lw); outH[wi] = hw;   outL[wi] = lw;
        split2(o.z, o.w, hw, lw); outH[wi+1] = hw; outL[wi+1] = lw;
    } else {
        __half2 h0 = __float22half2_rn(make_float2(o.x, o.y));
        __half2 h1 = __float22half2_rn(make_float2(o.z, o.w));
        outH[wi]   = *(uint32_t*)&h0;
        outH[wi+1] = *(uint32_t*)&h1;
    }
}

// ---------------------------------------------------------------------------
// bf16 3-term tensor GEMM (round-12 proven): 256 threads, 64x32 warp tile,
// BK=32, 2 buffers / 80KB smem, one __syncthreads per K-tile.
// ---------------------------------------------------------------------------
#define GSTR 20
#define GPL  (128*GSTR)
#define GEMM_SMEM (8*GPL*4)        // 81920 B

template<int RELU, int OUTMODE>
__global__ __launch_bounds__(256)
void gemm_bf16(const __nv_bfloat16* __restrict__ Ahp, const __nv_bfloat16* __restrict__ Alp,
               const __nv_bfloat16* __restrict__ Bhp, const __nv_bfloat16* __restrict__ Blp,
               const float* __restrict__ bias,
               float* __restrict__ C, uint32_t* __restrict__ Chw, uint32_t* __restrict__ Clw,
               int M, int N, int K)
{
    uint32_t* sm = (uint32_t*)dynsm;
    const int tid = threadIdx.x, warp = tid >> 5, lane = tid & 31;
    const int g = lane >> 2, c = lane & 3;
    const int bm = blockIdx.x * 128, bn = blockIdx.y * 128;
    const int wm = (warp >> 2) * 64, wn = (warp & 3) * 32;
    const uint32_t sb = smem_u32(sm);
    const int T = K / 32;

    const int alr = lane & 15, alw = (lane >> 4) * 4;
    const int blr = (lane & 7) + ((lane >> 4) << 3);
    const int blw = ((lane >> 3) & 1) * 4;

    auto stage = [&](int t, int b) {
        #pragma unroll
        for (int i = 0; i < 2; i++) {
            int id = tid + 256 * i, row = id >> 2, cc = id & 3;
            uint32_t doff = (uint32_t)(row * GSTR + cc * 4) * 4;
            uint32_t dbase = sb + (uint32_t)(b * 4 * GPL) * 4 + doff;
            long asrc = (long)(bm + row) * K + t * 32 + cc * 8;
            long bsrc = (long)(bn + row) * K + t * 32 + cc * 8;
            cpa16(dbase,             Ahp + asrc);
            cpa16(dbase + GPL*4,     Alp + asrc);
            cpa16(dbase + 2*GPL*4,   Bhp + bsrc);
            cpa16(dbase + 3*GPL*4,   Blp + bsrc);
        }
        asm volatile("cp.async.commit_group;");
    };

    float acc[4][4][4] = {};

    stage(0, 0);

    for (int t = 0; t < T; t++) {
        asm volatile("cp.async.wait_group 0;");
        __syncthreads();
        if (t + 1 < T) stage(t + 1, (t + 1) & 1);

        const uint32_t bufb = sb + (uint32_t)((t & 1) * 4 * GPL) * 4;

        #pragma unroll
        for (int kk = 0; kk < 2; kk++) {
            uint32_t ah[4][4], al[4][4];
            #pragma unroll
            for (int mt = 0; mt < 4; mt++) {
                uint32_t ao = (uint32_t)((wm + mt*16 + alr) * GSTR + kk*8 + alw) * 4;
                ldm4(ah[mt], bufb + ao);
                ldm4(al[mt], bufb + GPL*4 + ao);
            }
            #pragma unroll
            for (int pr = 0; pr < 2; pr++) {
                uint32_t bh[4], bl[4];
                uint32_t bo = (uint32_t)((wn + pr*16 + blr) * GSTR + kk*8 + blw) * 4;
                ldm4(bh, bufb + 2*GPL*4 + bo);
                ldm4(bl, bufb + 3*GPL*4 + bo);
                #pragma unroll
                for (int sub = 0; sub < 2; sub++) {
                    int nt = pr * 2 + sub;
                    #pragma unroll
                    for (int mt = 0; mt < 4; mt++) {
                        mma_bf16(acc[mt][nt], ah[mt], bh + 2*sub);
                        mma_bf16(acc[mt][nt], ah[mt], bl + 2*sub);
                        mma_bf16(acc[mt][nt], al[mt], bh + 2*sub);
                    }
                }
            }
        }
    }

    #pragma unroll
    for (int mt = 0; mt < 4; mt++) {
        #pragma unroll
        for (int nt = 0; nt < 4; nt++) {
            int col = bn + wn + nt*8 + 2*c;
            float bx = 0.f, by = 0.f;
            if (bias) { bx = bias[col]; by = bias[col + 1]; }
            long r0 = bm + wm + mt*16 + g;
            float v0 = acc[mt][nt][0] + bx, v1 = acc[mt][nt][1] + by;
            float v2 = acc[mt][nt][2] + bx, v3 = acc[mt][nt][3] + by;
            if (RELU) {
                v0 = fmaxf(v0, 0.f); v1 = fmaxf(v1, 0.f);
                v2 = fmaxf(v2, 0.f); v3 = fmaxf(v3, 0.f);
            }
            if (OUTMODE == 0) {
                *(float2*)(C + r0 * N + col)       = make_float2(v0, v1);
                *(float2*)(C + (r0 + 8) * N + col) = make_float2(v2, v3);
            } else {
                uint32_t hw, lw;
                split2(v0, v1, hw, lw);
                Chw[(r0 * N + col) >> 1] = hw; Clw[(r0 * N + col) >> 1] = lw;
                split2(v2, v3, hw, lw);
                Chw[((r0 + 8) * N + col) >> 1] = hw; Clw[((r0 + 8) * N + col) >> 1] = lw;
            }
        }
    }
}

// ---------------------------------------------------------------------------
// fp16 single-term GEMM (logits only): C = A[M,K](fp16) @ BT[N,K](fp16) + bias.
// 128x128x32 tiles, 2 smem planes -> 40KB, 2+ CTAs/SM.
// ---------------------------------------------------------------------------
#define F16_SMEM (4*GPL*4)     // 2 buffers x 2 planes = 40960 B

__global__ __launch_bounds__(256)
void gemm_f16(const __half* __restrict__ Ap, const __half* __restrict__ Bp,
              const float* __restrict__ bias, float* __restrict__ C,
              int M, int N, int K)
{
    uint32_t* sm = (uint32_t*)dynsm;
    const int tid = threadIdx.x, warp = tid >> 5, lane = tid & 31;
    const int g = lane >> 2, c = lane & 3;
    const int bm = blockIdx.x * 128, bn = blockIdx.y * 128;
    const int wm = (warp >> 2) * 64, wn = (warp & 3) * 32;
    const uint32_t sb = smem_u32(sm);
    const int T = K / 32;

    const int alr = lane & 15, alw = (lane >> 4) * 4;
    const int blr = (lane & 7) + ((lane >> 4) << 3);
    const int blw = ((lane >> 3) & 1) * 4;

    auto stage = [&](int t, int b) {
        #pragma unroll
        for (int i = 0; i < 2; i++) {
            int id = tid + 256 * i, row = id >> 2, cc = id & 3;
            uint32_t doff = (uint32_t)(row * GSTR + cc * 4) * 4;
            uint32_t dbase = sb + (uint32_t)(b * 2 * GPL) * 4 + doff;
            cpa16(dbase,         Ap + (long)(bm + row) * K + t * 32 + cc * 8);
            cpa16(dbase + GPL*4, Bp + (long)(bn + row) * K + t * 32 + cc * 8);
        }
        asm volatile("cp.async.commit_group;");
    };

    float acc[4][4][4] = {};

    stage(0, 0);

    for (int t = 0; t < T; t++) {
        asm volatile("cp.async.wait_group 0;");
        __syncthreads();
        if (t + 1 < T) stage(t + 1, (t + 1) & 1);

        const uint32_t bufb = sb + (uint32_t)((t & 1) * 2 * GPL) * 4;

        #pragma unroll
        for (int kk = 0; kk < 2; kk++) {
            uint32_t ah[4][4];
            #pragma unroll
            for (int mt = 0; mt < 4; mt++) {
                uint32_t ao = (uint32_t)((wm + mt*16 + alr) * GSTR + kk*8 + alw) * 4;
                ldm4(ah[mt], bufb + ao);
            }
            #pragma unroll
            for (int pr = 0; pr < 2; pr++) {
                uint32_t bh[4];
                uint32_t bo = (uint32_t)((wn + pr*16 + blr) * GSTR + kk*8 + blw) * 4;
                ldm4(bh, bufb + GPL*4 + bo);
                #pragma unroll
                for (int sub = 0; sub < 2; sub++) {
                    int nt = pr * 2 + sub;
                    #pragma unroll
                    for (int mt = 0; mt < 4; mt++)
                        mma_f16(acc[mt][nt], ah[mt], bh + 2*sub);
                }
            }
        }
    }

    #pragma unroll
    for (int mt = 0; mt < 4; mt++) {
        #pragma unroll
        for (int nt = 0; nt < 4; nt++) {
            int col = bn + wn + nt*8 + 2*c;
            float bx = bias[col], by = bias[col + 1];
            long r0 = bm + wm + mt*16 + g;
            *(float2*)(C + r0 * N + col) =
                make_float2(acc[mt][nt][0] + bx, acc[mt][nt][1] + by);
            *(float2*)(C + (r0 + 8) * N + col) =
                make_float2(acc[mt][nt][2] + bx, acc[mt][nt][3] + by);
        }
    }
}

// ---------------------------------------------------------------------------
// mma flash attention (round-8/12 known-good).
// ---------------------------------------------------------------------------
#define ASTR 36
#define AQH 0
#define AQL (128*ASTR)
#define AKH (2*128*ASTR)
#define AKL (AKH + 64*ASTR)
#define AVH (AKH + 2*64*ASTR)
#define AVL (AKH + 3*64*ASTR)
#define ATT_SMEM ((2*128*ASTR + 4*64*ASTR)*4)   // 73728 B

__global__ __launch_bounds__(256)
void attn_mma(const __nv_bfloat16* __restrict__ qh, const __nv_bfloat16* __restrict__ ql,
              uint32_t* __restrict__ oh, uint32_t* __restrict__ ol)
{
    uint32_t* sm = (uint32_t*)dynsm;
    const uint32_t sb = smem_u32(sm);
    const int tid = threadIdx.x, warp = tid >> 5, lane = tid & 31;
    const int g = lane >> 2, c = lane & 3;
    const int qt = (int)gridDim.x - 1 - (int)blockIdx.x;
    const int h = blockIdx.y, b = blockIdx.z;
    const long rowbase = (long)b * SS;
    const int qoff = h << 6;

    const int alr = lane & 15, alw = (lane >> 4) * 4;
    const int blr = (lane & 7) + ((lane >> 4) << 3);
    const int blw = ((lane >> 3) & 1) * 4;
    const int vlr = ((lane >> 3) & 1) * 8 + (lane & 7);
    const int vlw = (lane >> 4) * 4;

    #pragma unroll
    for (int p = 0; p < 2; p++) {
        const __nv_bfloat16* src = p ? ql : qh;
        uint32_t dst = sb + (p ? AQL : AQH) * 4;
        #pragma unroll
        for (int i = 0; i < 4; i++) {
            int id = tid + 256 * i;
            int row = id >> 3, ch = id & 7;
            cpa16(dst + (uint32_t)(row * ASTR + ch * 4) * 4,
                  src + (rowbase + qt * 128 + row) * 1536 + qoff + ch * 8);
        }
    }
    asm volatile("cp.async.commit_group;");
    asm volatile("cp.async.wait_group 0;");
    __syncthreads();

    uint32_t Qh[4][4], Ql[4][4];
    #pragma unroll
    for (int kk = 0; kk < 4; kk++) {
        uint32_t qo = (uint32_t)((warp*16 + alr) * ASTR + kk*8 + alw) * 4;
        ldm4(Qh[kk], sb + AQH*4 + qo);
        ldm4(Ql[kk], sb + AQL*4 + qo);
    }

    float m0 = -1e30f, m1 = -1e30f, l0 = 0.f, l1 = 0.f;
    float O[8][4] = {};
    const int nk = 2 * qt + 2;
    const int rbase = qt * 128 + warp * 16;

    for (int kt = 0; kt < nk; kt++) {
        #pragma unroll
        for (int i = 0; i < 8; i++) {
            int id = tid + 256 * i;
            int p  = (id >> 9) & 1;
            int kv = id >> 10;
            int rem = id & 511;
            int row = rem >> 3, ch = rem & 7;
            const __nv_bfloat16* src = p ? ql : qh;
            uint32_t base = kv ? (p ? AVL : AVH) : (p ? AKL : AKH);
            cpa16(sb + (uint32_t)(base + row * ASTR + ch * 4) * 4,
                  src + (rowbase + kt * 64 + row) * 1536 + (kv ? 1024 : 512) + qoff + ch * 8);
        }
        asm volatile("cp.async.commit_group;");
        asm volatile("cp.async.wait_group 0;");
        __syncthreads();

        float sacc[8][4] = {};
        #pragma unroll
        for (int kk = 0; kk < 4; kk++) {
            #pragma unroll
            for (int pr = 0; pr < 4; pr++) {
                uint32_t bh[4], bl[4];
                uint32_t bo = (uint32_t)((pr*16 + blr) * ASTR + kk*8 + blw) * 4;
                ldm4(bh, sb + AKH*4 + bo);
                ldm4(bl, sb + AKL*4 + bo);
                #pragma unroll
                for (int sub = 0; sub < 2; sub++) {
                    int nt = pr * 2 + sub;
                    mma_bf16(sacc[nt], Qh[kk], bh + 2*sub);
                    mma_bf16(sacc[nt], Qh[kk], bl + 2*sub);
                    mma_bf16(sacc[nt], Ql[kk], bh + 2*sub);
                }
            }
        }

        const float scale = 0.125f;
        const bool diag = (kt >= 2 * qt);
        const int row0 = rbase + g, row1 = rbase + g + 8;
        const int colb = kt * 64 + 2 * c;
        float rm0 = -1e30f, rm1 = -1e30f;
        #pragma unroll
        for (int nt = 0; nt < 8; nt++) {
            int c0 = colb + nt * 8;
            float v0 = sacc[nt][0] * scale, v1 = sacc[nt][1] * scale;
            float v2 = sacc[nt][2] * scale, v3 = sacc[nt][3] * scale;
            if (diag) {
                if (c0     > row0) v0 = -1e30f;
                if (c0 + 1 > row0) v1 = -1e30f;
                if (c0     > row1) v2 = -1e30f;
                if (c0 + 1 > row1) v3 = -1e30f;
            }
            sacc[nt][0] = v0; sacc[nt][1] = v1; sacc[nt][2] = v2; sacc[nt][3] = v3;
            rm0 = fmaxf(rm0, fmaxf(v0, v1));
            rm1 = fmaxf(rm1, fmaxf(v2, v3));
        }
        #pragma unroll
        for (int o = 1; o < 4; o <<= 1) {
            rm0 = fmaxf(rm0, __shfl_xor_sync(0xffffffffu, rm0, o));
            rm1 = fmaxf(rm1, __shfl_xor_sync(0xffffffffu, rm1, o));
        }
        float nm0 = fmaxf(m0, rm0), nm1 = fmaxf(m1, rm1);
        float sf0 = __expf(m0 - nm0), sf1 = __expf(m1 - nm1);
        m0 = nm0; m1 = nm1;
        float rs0 = 0.f, rs1 = 0.f;
        #pragma unroll
        for (int nt = 0; nt < 8; nt++) {
            float p0 = __expf(sacc[nt][0] - nm0);
            float p1 = __expf(sacc[nt][1] - nm0);
            float p2 = __expf(sacc[nt][2] - nm1);
            float p3 = __expf(sacc[nt][3] - nm1);
            sacc[nt][0] = p0; sacc[nt][1] = p1; sacc[nt][2] = p2; sacc[nt][3] = p3;
            rs0 += p0 + p1; rs1 += p2 + p3;
        }
        #pragma unroll
        for (int o = 1; o < 4; o <<= 1) {
            rs0 += __shfl_xor_sync(0xffffffffu, rs0, o);
            rs1 += __shfl_xor_sync(0xffffffffu, rs1, o);
        }
        l0 = l0 * sf0 + rs0;
        l1 = l1 * sf1 + rs1;
        #pragma unroll
        for (int nt = 0; nt < 8; nt++) {
            O[nt][0] *= sf0; O[nt][1] *= sf0;
            O[nt][2] *= sf1; O[nt][3] *= sf1;
        }

        #pragma unroll
        for (int kk = 0; kk < 4; kk++) {
            uint32_t ah[4], al[4];
            split2(sacc[2*kk][0],   sacc[2*kk][1],   ah[0], al[0]);
            split2(sacc[2*kk][2],   sacc[2*kk][3],   ah[1], al[1]);
            split2(sacc[2*kk+1][0], sacc[2*kk+1][1], ah[2], al[2]);
            split2(sacc[2*kk+1][2], sacc[2*kk+1][3], ah[3], al[3]);
            #pragma unroll
            for (int pr = 0; pr < 4; pr++) {
                uint32_t bh[4], bl[4];
                uint32_t vo = (uint32_t)((kk*16 + vlr) * ASTR + pr*8 + vlw) * 4;
                ldm4t(bh, sb + AVH*4 + vo);
                ldm4t(bl, sb + AVL*4 + vo);
                #pragma unroll
                for (int sub = 0; sub < 2; sub++) {
                    int nt = pr * 2 + sub;
                    mma_bf16(O[nt], ah, bh + 2*sub);
                    mma_bf16(O[nt], ah, bl + 2*sub);
                    mma_bf16(O[nt], al, bh + 2*sub);
                }
            }
        }
        __syncthreads();
    }

    float inv0 = 1.0f / l0, inv1 = 1.0f / l1;
    long grow0 = rowbase + rbase + g;
    #pragma unroll
    for (int nt = 0; nt < 8; nt++) {
        int col = qoff + nt * 8 + 2 * c;
        uint32_t hw, lw;
        split2(O[nt][0] * inv0, O[nt][1] * inv0, hw, lw);
        oh[(grow0 * DD + col) >> 1] = hw;
        ol[(grow0 * DD + col) >> 1] = lw;
        split2(O[nt][2] * inv1, O[nt][3] * inv1, hw, lw);
        oh[((grow0 + 8) * DD + col) >> 1] = hw;
        ol[((grow0 + 8) * DD + col) >> 1] = lw;
    }
}

// ---------------------------------------------------------------------------
extern "C" void kernel_launch(void* const* d_in, const int* in_sizes, int n_in,
                              void* d_out, int out_size)
{
    const int*   x    = (const int*)  d_in[0];
    const float* emb  = (const float*)d_in[1];
    const float* pe   = (const float*)d_in[2];
    const float* Wqkv = (const float*)d_in[3];
    const float* Wo   = (const float*)d_in[4];
    const float* bo   = (const float*)d_in[5];
    const float* g1   = (const float*)d_in[6];
    const float* b1   = (const float*)d_in[7];
    const float* g2   = (const float*)d_in[8];
    const float* b2   = (const float*)d_in[9];
    const float* W1   = (const float*)d_in[10];
    const float* bf1  = (const float*)d_in[11];
    const float* W2   = (const float*)d_in[12];
    const float* bf2  = (const float*)d_in[13];
    const float* gf   = (const float*)d_in[14];
    const float* bfp  = (const float*)d_in[15];
    const float* Wout = (const float*)d_in[16];
    const float* bfc  = (const float*)d_in[17];
    float* out = (float*)d_out;

    float *h, *t;
    cudaGetSymbolAddress((void**)&h, g_h);
    cudaGetSymbolAddress((void**)&t, g_t);
    __nv_bfloat16 *hh, *hl, *qh, *ql, *oh, *ol, *fh, *fl;
    __half *tf, *outTf;
    cudaGetSymbolAddress((void**)&hh, g_hh);  cudaGetSymbolAddress((void**)&hl, g_hl);
    cudaGetSymbolAddress((void**)&qh, g_qh);  cudaGetSymbolAddress((void**)&ql, g_ql);
    cudaGetSymbolAddress((void**)&oh, g_oh);  cudaGetSymbolAddress((void**)&ol, g_ol);
    cudaGetSymbolAddress((void**)&fh, g_fh);  cudaGetSymbolAddress((void**)&fl, g_fl);
    cudaGetSymbolAddress((void**)&tf, g_tf);
    cudaGetSymbolAddress((void**)&outTf, g_outT_f);
    __nv_bfloat16 *qkvTh, *qkvTl, *woTh, *woTl, *w1Th, *w1Tl, *w2Th, *w2Tl;
    cudaGetSymbolAddress((void**)&qkvTh, g_qkvT_h);
    cudaGetSymbolAddress((void**)&qkvTl, g_qkvT_l);
    cudaGetSymbolAddress((void**)&woTh,  g_woT_h);
    cudaGetSymbolAddress((void**)&woTl,  g_woT_l);
    cudaGetSymbolAddress((void**)&w1Th,  g_w1T_h);
    cudaGetSymbolAddress((void**)&w1Tl,  g_w1T_l);
    cudaGetSymbolAddress((void**)&w2Th,  g_w2T_h);
    cudaGetSymbolAddress((void**)&w2Tl,  g_w2T_l);

    cudaFuncSetAttribute(attn_mma, cudaFuncAttributeMaxDynamicSharedMemorySize, ATT_SMEM);
    cudaFuncSetAttribute(gemm_bf16<0,0>, cudaFuncAttributeMaxDynamicSharedMemorySize, GEMM_SMEM);
    cudaFuncSetAttribute(gemm_bf16<0,1>, cudaFuncAttributeMaxDynamicSharedMemorySize, GEMM_SMEM);
    cudaFuncSetAttribute(gemm_bf16<1,1>, cudaFuncAttributeMaxDynamicSharedMemorySize, GEMM_SMEM);
    cudaFuncSetAttribute(gemm_f16, cudaFuncAttributeMaxDynamicSharedMemorySize, F16_SMEM);

    wprep_k<<<dim3(3*DD/32, DD/32, LL), 256>>>(Wqkv, qkvTh, qkvTl, DD, 3*DD);
    wprep_k<<<dim3(DD/32,   DD/32, LL), 256>>>(Wo,   woTh,  woTl,  DD, DD);
    wprep_k<<<dim3(FF/32,   DD/32, LL), 256>>>(W1,   w1Th,  w1Tl,  DD, FF);
    wprep_k<<<dim3(DD/32,   FF/32, LL), 256>>>(W2,   w2Th,  w2Tl,  FF, DD);
    wprep16_k<<<dim3(VV/32, DD/32), 256>>>(Wout, outTf, DD, VV);

    embed_k<<<ROWS, 128>>>(x, emb, pe, h, (uint32_t*)hh, (uint32_t*)hl);

    for (int l = 0; l < LL; l++) {
        gemm_bf16<0,1><<<dim3(32, 12), 256, GEMM_SMEM>>>(
            hh, hl, qkvTh + (long)l * 3*DD*DD, qkvTl + (long)l * 3*DD*DD,
            nullptr, nullptr, (uint32_t*)qh, (uint32_t*)ql, ROWS, 3*DD, DD);
        attn_mma<<<dim3(SS/128, HH, BB), 256, ATT_SMEM>>>(
            qh, ql, (uint32_t*)oh, (uint32_t*)ol);
        gemm_bf16<0,0><<<dim3(32, 4), 256, GEMM_SMEM>>>(
            oh, ol, woTh + (long)l * DD*DD, woTl + (long)l * DD*DD,
            bo + l * DD, t, nullptr, nullptr, ROWS, DD, DD);
        add_ln_k<0><<<ROWS, 128>>>(t, h, g1 + l * DD, b1 + l * DD,
                                   h, (uint32_t*)hh, (uint32_t*)hl);
        gemm_bf16<1,1><<<dim3(32, 16), 256, GEMM_SMEM>>>(
            hh, hl, w1Th + (long)l * FF*DD, w1Tl + (long)l * FF*DD,
            bf1 + l * FF, nullptr, (uint32_t*)fh, (uint32_t*)fl, ROWS, FF, DD);
        gemm_bf16<0,0><<<dim3(32, 4), 256, GEMM_SMEM>>>(
            fh, fl, w2Th + (long)l * DD*FF, w2Tl + (long)l * DD*FF,
            bf2 + l * DD, t, nullptr, nullptr, ROWS, DD, FF);
        add_ln_k<0><<<ROWS, 128>>>(t, h, g2 + l * DD, b2 + l * DD,
                                   h, (uint32_t*)hh, (uint32_t*)hl);
    }

    // final LN -> packed fp16 plane
    add_ln_k<1><<<ROWS, 128>>>(h, nullptr, gf, bfp, t, (uint32_t*)tf, nullptr);
    // logits: fp16 single-term GEMM
    gemm_f16<<<dim3(32, 250), 256, F16_SMEM>>>(tf, outTf, bfc, out, ROWS, VV, DD);
}

// round 14
// speedup vs baseline: 2.3080x; 1.2145x over previous
#include <cuda_runtime.h>
#include <cuda_bf16.h>
#include <cuda_fp16.h>
#include <cstdint>

#define BB 2
#define SS 2048
#define DD 512
#define LL 6
#define HH 8
#define FF 2048
#define VV 32000
#define ROWS (BB*SS)   // 4096

// fp32 residual stream scratch
__device__ float g_h [ROWS * DD];
__device__ float g_t [ROWS * DD];
// packed bf16 hi/lo activation planes
__device__ __align__(16) __nv_bfloat16 g_hh [ROWS * DD],  g_hl [ROWS * DD];
__device__ __align__(16) __nv_bfloat16 g_oh [ROWS * DD],  g_ol [ROWS * DD];
__device__ __align__(16) __nv_bfloat16 g_fh [ROWS * FF],  g_fl [ROWS * FF];
// fp16 single planes
__device__ __align__(16) __half g_qf [ROWS * 3*DD];   // qkv for attention
__device__ __align__(16) __half g_tf [ROWS * DD];     // final LN output
// pre-transposed bf16-split weights: [N][K] row-major
__device__ __align__(16) __nv_bfloat16 g_qkvT_h[LL * 3*DD * DD], g_qkvT_l[LL * 3*DD * DD];
__device__ __align__(16) __nv_bfloat16 g_woT_h [LL * DD * DD],   g_woT_l [LL * DD * DD];
__device__ __align__(16) __nv_bfloat16 g_w1T_h [LL * FF * DD],   g_w1T_l [LL * FF * DD];
__device__ __align__(16) __nv_bfloat16 g_w2T_h [LL * DD * FF],   g_w2T_l [LL * DD * FF];
// fp16 single-plane transposed Wout
__device__ __align__(16) __half g_outT_f[VV * DD];

extern __shared__ char dynsm[];

// ---------------------------------------------------------------------------
__device__ __forceinline__ uint32_t smem_u32(const void* p) {
    uint32_t a;
    asm("{ .reg .u64 t; cvta.to.shared.u64 t, %1; cvt.u32.u64 %0, t; }"
        : "=r"(a) : "l"(p));
    return a;
}
__device__ __forceinline__ void cpa16(uint32_t s, const void* g) {
    asm volatile("cp.async.cg.shared.global [%0], [%1], 16;" :: "r"(s), "l"(g));
}
__device__ __forceinline__ void split2(float x0, float x1, uint32_t& hw, uint32_t& lw) {
    __nv_bfloat16 h0 = __float2bfloat16(x0), h1 = __float2bfloat16(x1);
    __nv_bfloat16 l0 = __float2bfloat16(x0 - __bfloat162float(h0));
    __nv_bfloat16 l1 = __float2bfloat16(x1 - __bfloat162float(h1));
    __nv_bfloat162 hp(h0, h1), lp(l0, l1);
    hw = *(uint32_t*)&hp;
    lw = *(uint32_t*)&lp;
}
__device__ __forceinline__ uint32_t packh2(float x0, float x1) {
    __half2 p = __float22half2_rn(make_float2(x0, x1));
    return *(uint32_t*)&p;
}
__device__ __forceinline__ void mma_bf16(float* d, const uint32_t* a, const uint32_t* b) {
    asm volatile("mma.sync.aligned.m16n8k16.row.col.f32.bf16.bf16.f32 "
        "{%0,%1,%2,%3}, {%4,%5,%6,%7}, {%8,%9}, {%0,%1,%2,%3};"
        : "+f"(d[0]), "+f"(d[1]), "+f"(d[2]), "+f"(d[3])
        : "r"(a[0]), "r"(a[1]), "r"(a[2]), "r"(a[3]), "r"(b[0]), "r"(b[1]));
}
__device__ __forceinline__ void mma_f16(float* d, const uint32_t* a, const uint32_t* b) {
    asm volatile("mma.sync.aligned.m16n8k16.row.col.f32.f16.f16.f32 "
        "{%0,%1,%2,%3}, {%4,%5,%6,%7}, {%8,%9}, {%0,%1,%2,%3};"
        : "+f"(d[0]), "+f"(d[1]), "+f"(d[2]), "+f"(d[3])
        : "r"(a[0]), "r"(a[1]), "r"(a[2]), "r"(a[3]), "r"(b[0]), "r"(b[1]));
}
__device__ __forceinline__ void ldm4(uint32_t* r, uint32_t a) {
    asm volatile("ldmatrix.sync.aligned.m8n8.x4.shared.b16 {%0,%1,%2,%3}, [%4];"
        : "=r"(r[0]), "=r"(r[1]), "=r"(r[2]), "=r"(r[3]) : "r"(a));
}
__device__ __forceinline__ void ldm4t(uint32_t* r, uint32_t a) {
    asm volatile("ldmatrix.sync.aligned.m8n8.x4.trans.shared.b16 {%0,%1,%2,%3}, [%4];"
        : "=r"(r[0]), "=r"(r[1]), "=r"(r[2]), "=r"(r[3]) : "r"(a));
}

// ---------------------------------------------------------------------------
// Weight prep: W[K,N] fp32 -> WT hi/lo [N,K] bf16
// ---------------------------------------------------------------------------
__global__ void wprep_k(const float* __restrict__ W, __nv_bfloat16* __restrict__ hi,
                        __nv_bfloat16* __restrict__ lo, int K, int N)
{
    __shared__ float ts[32][33];
    long moff = (long)blockIdx.z * K * N;
    int kb = blockIdx.y * 32, nb = blockIdx.x * 32;
    int r = threadIdx.x >> 5, c = threadIdx.x & 31;
    #pragma unroll
    for (int i = 0; i < 4; i++)
        ts[r + i*8][c] = W[moff + (long)(kb + r + i*8) * N + nb + c];
    __syncthreads();
    #pragma unroll
    for (int i = 0; i < 4; i++) {
        int n = r + i*8;
        float x = ts[c][n];
        __nv_bfloat16 h = __float2bfloat16(x);
        __nv_bfloat16 l = __float2bfloat16(x - __bfloat162float(h));
        long oidx = moff + (long)(nb + n) * K + kb + c;
        hi[oidx] = h;
        lo[oidx] = l;
    }
}

// Weight prep fp16 single plane: W[K,N] fp32 -> WT [N,K] fp16
__global__ void wprep16_k(const float* __restrict__ W, __half* __restrict__ o,
                          int K, int N)
{
    __shared__ float ts[32][33];
    int kb = blockIdx.y * 32, nb = blockIdx.x * 32;
    int r = threadIdx.x >> 5, c = threadIdx.x & 31;
    #pragma unroll
    for (int i = 0; i < 4; i++)
        ts[r + i*8][c] = W[(long)(kb + r + i*8) * N + nb + c];
    __syncthreads();
    #pragma unroll
    for (int i = 0; i < 4; i++) {
        int n = r + i*8;
        o[(long)(nb + n) * K + kb + c] = __float2half_rn(ts[c][n]);
    }
}

// ---------------------------------------------------------------------------
// Embedding + PE -> fp32 h + hi/lo planes
// ---------------------------------------------------------------------------
__global__ void embed_k(const int* __restrict__ x, const float* __restrict__ emb,
                        const float* __restrict__ pe, float* __restrict__ h,
                        uint32_t* __restrict__ oh, uint32_t* __restrict__ ol)
{
    int row = blockIdx.x, tid = threadIdx.x;
    int s   = row & (SS - 1);
    int tok = x[row];
    float4 ev = ((const float4*)(emb + (long)tok * DD))[tid];
    float4 pv = ((const float4*)(pe  + (long)s   * DD))[tid];
    float4 o;
    o.x = ev.x + pv.x; o.y = ev.y + pv.y; o.z = ev.z + pv.z; o.w = ev.w + pv.w;
    ((float4*)(h + (long)row * DD))[tid] = o;
    uint32_t hw, lw;
    int wi = row * (DD/2) + tid * 2;
    split2(o.x, o.y, hw, lw); oh[wi] = hw;   ol[wi] = lw;
    split2(o.z, o.w, hw, lw); oh[wi+1] = hw; ol[wi+1] = lw;
}

// ---------------------------------------------------------------------------
// out = LayerNorm(x (+ res)) * g + b.
// MODE 0: fp32 + bf16 hi/lo planes.  MODE 1: fp32 + packed fp16 plane (outH).
// ---------------------------------------------------------------------------
template<int MODE>
__global__ void add_ln_k(const float* __restrict__ x, const float* __restrict__ res,
                         const float* __restrict__ gg, const float* __restrict__ bb,
                         float* __restrict__ outF,
                         uint32_t* __restrict__ outH, uint32_t* __restrict__ outL)
{
    int row = blockIdx.x, tid = threadIdx.x;
    float4 v = ((const float4*)(x + (long)row * DD))[tid];
    if (res) {
        float4 rv = ((const float4*)(res + (long)row * DD))[tid];
        v.x += rv.x; v.y += rv.y; v.z += rv.z; v.w += rv.w;
    }
    float s  = v.x + v.y + v.z + v.w;
    float s2 = v.x*v.x + v.y*v.y + v.z*v.z + v.w*v.w;
    #pragma unroll
    for (int o = 16; o; o >>= 1) {
        s  += __shfl_xor_sync(0xffffffffu, s,  o);
        s2 += __shfl_xor_sync(0xffffffffu, s2, o);
    }
    __shared__ float ssum[4], ssq[4];
    int wid = tid >> 5;
    if ((tid & 31) == 0) { ssum[wid] = s; ssq[wid] = s2; }
    __syncthreads();
    s  = ssum[0] + ssum[1] + ssum[2] + ssum[3];
    s2 = ssq[0]  + ssq[1]  + ssq[2]  + ssq[3];
    float mean = s * (1.0f / DD);
    float var  = s2 * (1.0f / DD) - mean * mean;
    float inv  = rsqrtf(var + 1e-5f);
    float4 gv = ((const float4*)gg)[tid];
    float4 bv = ((const float4*)bb)[tid];
    float4 o;
    o.x = (v.x - mean) * inv * gv.x + bv.x;
    o.y = (v.y - mean) * inv * gv.y + bv.y;
    o.z = (v.z - mean) * inv * gv.z + bv.z;
    o.w = (v.w - mean) * inv * gv.w + bv.w;
    ((float4*)(outF + (long)row * DD))[tid] = o;
    int wi = row * (DD/2) + tid * 2;
    if (MODE == 0) {
        uint32_t hw, lw;
        split2(o.x, o.y, hw, lw); outH[wi] = hw;   outL[wi] = lw;
        split2(o.z, o.w, hw, lw); outH[wi+1] = hw; outL[wi+1] = lw;
    } else {
        outH[wi]   = packh2(o.x, o.y);
        outH[wi+1] = packh2(o.z, o.w);
    }
}

// ---------------------------------------------------------------------------
// bf16 3-term tensor GEMM (round-12 proven): 256 threads, 64x32 warp tile,
// BK=32, 2 buffers / 80KB smem, one __syncthreads per K-tile.
// OUTMODE 0: fp32. OUTMODE 1: bf16 hi/lo planes. OUTMODE 2: fp16 plane.
// ---------------------------------------------------------------------------
#define GSTR 20
#define GPL  (128*GSTR)
#define GEMM_SMEM (8*GPL*4)        // 81920 B

template<int RELU, int OUTMODE>
__global__ __launch_bounds__(256)
void gemm_bf16(const __nv_bfloat16* __restrict__ Ahp, const __nv_bfloat16* __restrict__ Alp,
               const __nv_bfloat16* __restrict__ Bhp, const __nv_bfloat16* __restrict__ Blp,
               const float* __restrict__ bias,
               float* __restrict__ C, uint32_t* __restrict__ Chw, uint32_t* __restrict__ Clw,
               int M, int N, int K)
{
    uint32_t* sm = (uint32_t*)dynsm;
    const int tid = threadIdx.x, warp = tid >> 5, lane = tid & 31;
    const int g = lane >> 2, c = lane & 3;
    const int bm = blockIdx.x * 128, bn = blockIdx.y * 128;
    const int wm = (warp >> 2) * 64, wn = (warp & 3) * 32;
    const uint32_t sb = smem_u32(sm);
    const int T = K / 32;

    const int alr = lane & 15, alw = (lane >> 4) * 4;
    const int blr = (lane & 7) + ((lane >> 4) << 3);
    const int blw = ((lane >> 3) & 1) * 4;

    auto stage = [&](int t, int b) {
        #pragma unroll
        for (int i = 0; i < 2; i++) {
            int id = tid + 256 * i, row = id >> 2, cc = id & 3;
            uint32_t doff = (uint32_t)(row * GSTR + cc * 4) * 4;
            uint32_t dbase = sb + (uint32_t)(b * 4 * GPL) * 4 + doff;
            long asrc = (long)(bm + row) * K + t * 32 + cc * 8;
            long bsrc = (long)(bn + row) * K + t * 32 + cc * 8;
            cpa16(dbase,             Ahp + asrc);
            cpa16(dbase + GPL*4,     Alp + asrc);
            cpa16(dbase + 2*GPL*4,   Bhp + bsrc);
            cpa16(dbase + 3*GPL*4,   Blp + bsrc);
        }
        asm volatile("cp.async.commit_group;");
    };

    float acc[4][4][4] = {};

    stage(0, 0);

    for (int t = 0; t < T; t++) {
        asm volatile("cp.async.wait_group 0;");
        __syncthreads();
        if (t + 1 < T) stage(t + 1, (t + 1) & 1);

        const uint32_t bufb = sb + (uint32_t)((t & 1) * 4 * GPL) * 4;

        #pragma unroll
        for (int kk = 0; kk < 2; kk++) {
            uint32_t ah[4][4], al[4][4];
            #pragma unroll
            for (int mt = 0; mt < 4; mt++) {
                uint32_t ao = (uint32_t)((wm + mt*16 + alr) * GSTR + kk*8 + alw) * 4;
                ldm4(ah[mt], bufb + ao);
                ldm4(al[mt], bufb + GPL*4 + ao);
            }
            #pragma unroll
            for (int pr = 0; pr < 2; pr++) {
                uint32_t bh[4], bl[4];
                uint32_t bo = (uint32_t)((wn + pr*16 + blr) * GSTR + kk*8 + blw) * 4;
                ldm4(bh, bufb + 2*GPL*4 + bo);
                ldm4(bl, bufb + 3*GPL*4 + bo);
                #pragma unroll
                for (int sub = 0; sub < 2; sub++) {
                    int nt = pr * 2 + sub;
                    #pragma unroll
                    for (int mt = 0; mt < 4; mt++) {
                        mma_bf16(acc[mt][nt], ah[mt], bh + 2*sub);
                        mma_bf16(acc[mt][nt], ah[mt], bl + 2*sub);
                        mma_bf16(acc[mt][nt], al[mt], bh + 2*sub);
                    }
                }
            }
        }
    }

    #pragma unroll
    for (int mt = 0; mt < 4; mt++) {
        #pragma unroll
        for (int nt = 0; nt < 4; nt++) {
            int col = bn + wn + nt*8 + 2*c;
            float bx = 0.f, by = 0.f;
            if (bias) { bx = bias[col]; by = bias[col + 1]; }
            long r0 = bm + wm + mt*16 + g;
            float v0 = acc[mt][nt][0] + bx, v1 = acc[mt][nt][1] + by;
            float v2 = acc[mt][nt][2] + bx, v3 = acc[mt][nt][3] + by;
            if (RELU) {
                v0 = fmaxf(v0, 0.f); v1 = fmaxf(v1, 0.f);
                v2 = fmaxf(v2, 0.f); v3 = fmaxf(v3, 0.f);
            }
            if (OUTMODE == 0) {
                *(float2*)(C + r0 * N + col)       = make_float2(v0, v1);
                *(float2*)(C + (r0 + 8) * N + col) = make_float2(v2, v3);
            } else if (OUTMODE == 1) {
                uint32_t hw, lw;
                split2(v0, v1, hw, lw);
                Chw[(r0 * N + col) >> 1] = hw; Clw[(r0 * N + col) >> 1] = lw;
                split2(v2, v3, hw, lw);
                Chw[((r0 + 8) * N + col) >> 1] = hw; Clw[((r0 + 8) * N + col) >> 1] = lw;
            } else {
                Chw[(r0 * N + col) >> 1]       = packh2(v0, v1);
                Chw[((r0 + 8) * N + col) >> 1] = packh2(v2, v3);
            }
        }
    }
}

// ---------------------------------------------------------------------------
// fp16 single-term GEMM (logits): C = A[M,K](fp16) @ BT[N,K](fp16) + bias.
// ---------------------------------------------------------------------------
#define F16_SMEM (4*GPL*4)     // 40960 B

__global__ __launch_bounds__(256)
void gemm_f16(const __half* __restrict__ Ap, const __half* __restrict__ Bp,
              const float* __restrict__ bias, float* __restrict__ C,
              int M, int N, int K)
{
    uint32_t* sm = (uint32_t*)dynsm;
    const int tid = threadIdx.x, warp = tid >> 5, lane = tid & 31;
    const int g = lane >> 2, c = lane & 3;
    const int bm = blockIdx.x * 128, bn = blockIdx.y * 128;
    const int wm = (warp >> 2) * 64, wn = (warp & 3) * 32;
    const uint32_t sb = smem_u32(sm);
    const int T = K / 32;

    const int alr = lane & 15, alw = (lane >> 4) * 4;
    const int blr = (lane & 7) + ((lane >> 4) << 3);
    const int blw = ((lane >> 3) & 1) * 4;

    auto stage = [&](int t, int b) {
        #pragma unroll
        for (int i = 0; i < 2; i++) {
            int id = tid + 256 * i, row = id >> 2, cc = id & 3;
            uint32_t doff = (uint32_t)(row * GSTR + cc * 4) * 4;
            uint32_t dbase = sb + (uint32_t)(b * 2 * GPL) * 4 + doff;
            cpa16(dbase,         Ap + (long)(bm + row) * K + t * 32 + cc * 8);
            cpa16(dbase + GPL*4, Bp + (long)(bn + row) * K + t * 32 + cc * 8);
        }
        asm volatile("cp.async.commit_group;");
    };

    float acc[4][4][4] = {};

    stage(0, 0);

    for (int t = 0; t < T; t++) {
        asm volatile("cp.async.wait_group 0;");
        __syncthreads();
        if (t + 1 < T) stage(t + 1, (t + 1) & 1);

        const uint32_t bufb = sb + (uint32_t)((t & 1) * 2 * GPL) * 4;

        #pragma unroll
        for (int kk = 0; kk < 2; kk++) {
            uint32_t ah[4][4];
            #pragma unroll
            for (int mt = 0; mt < 4; mt++) {
                uint32_t ao = (uint32_t)((wm + mt*16 + alr) * GSTR + kk*8 + alw) * 4;
                ldm4(ah[mt], bufb + ao);
            }
            #pragma unroll
            for (int pr = 0; pr < 2; pr++) {
                uint32_t bh[4];
                uint32_t bo = (uint32_t)((wn + pr*16 + blr) * GSTR + kk*8 + blw) * 4;
                ldm4(bh, bufb + GPL*4 + bo);
                #pragma unroll
                for (int sub = 0; sub < 2; sub++) {
                    int nt = pr * 2 + sub;
                    #pragma unroll
                    for (int mt = 0; mt < 4; mt++)
                        mma_f16(acc[mt][nt], ah[mt], bh + 2*sub);
                }
            }
        }
    }

    #pragma unroll
    for (int mt = 0; mt < 4; mt++) {
        #pragma unroll
        for (int nt = 0; nt < 4; nt++) {
            int col = bn + wn + nt*8 + 2*c;
            float bx = bias[col], by = bias[col + 1];
            long r0 = bm + wm + mt*16 + g;
            *(float2*)(C + r0 * N + col) =
                make_float2(acc[mt][nt][0] + bx, acc[mt][nt][1] + by);
            *(float2*)(C + (r0 + 8) * N + col) =
                make_float2(acc[mt][nt][2] + bx, acc[mt][nt][3] + by);
        }
    }
}

// ---------------------------------------------------------------------------
// fp16 single-term flash attention. QKV as one fp16 plane [row][1536].
// CTA = 128 q-rows x (head, batch), 8 warps x 16 rows. Output: bf16 hi/lo.
// ---------------------------------------------------------------------------
#define ASTR 36
#define AQF 0
#define AKF (128*ASTR)          // 4608 words
#define AVF (AKF + 64*ASTR)     // 6912 words
#define ATTF_SMEM ((128*ASTR + 2*64*ASTR)*4)   // 36864 B

__global__ __launch_bounds__(256)
void attn_f16(const __half* __restrict__ qf,
              uint32_t* __restrict__ oh, uint32_t* __restrict__ ol)
{
    uint32_t* sm = (uint32_t*)dynsm;
    const uint32_t sb = smem_u32(sm);
    const int tid = threadIdx.x, warp = tid >> 5, lane = tid & 31;
    const int g = lane >> 2, c = lane & 3;
    const int qt = (int)gridDim.x - 1 - (int)blockIdx.x;
    const int h = blockIdx.y, b = blockIdx.z;
    const long rowbase = (long)b * SS;
    const int qoff = h << 6;

    const int alr = lane & 15, alw = (lane >> 4) * 4;
    const int blr = (lane & 7) + ((lane >> 4) << 3);
    const int blw = ((lane >> 3) & 1) * 4;
    const int vlr = ((lane >> 3) & 1) * 8 + (lane & 7);
    const int vlw = (lane >> 4) * 4;

    // stage Q (128 rows x 64 fp16)
    #pragma unroll
    for (int i = 0; i < 4; i++) {
        int id = tid + 256 * i;
        int row = id >> 3, ch = id & 7;
        cpa16(sb + (uint32_t)(AQF + row * ASTR + ch * 4) * 4,
              qf + (rowbase + qt * 128 + row) * 1536 + qoff + ch * 8);
    }
    asm volatile("cp.async.commit_group;");
    asm volatile("cp.async.wait_group 0;");
    __syncthreads();

    // hoist Q fragments (4 k-chunks)
    uint32_t Qf[4][4];
    #pragma unroll
    for (int kk = 0; kk < 4; kk++) {
        uint32_t qo = (uint32_t)((warp*16 + alr) * ASTR + kk*8 + alw) * 4;
        ldm4(Qf[kk], sb + AQF*4 + qo);
    }

    float m0 = -1e30f, m1 = -1e30f, l0 = 0.f, l1 = 0.f;
    float O[8][4] = {};
    const int nk = 2 * qt + 2;
    const int rbase = qt * 128 + warp * 16;

    for (int kt = 0; kt < nk; kt++) {
        // stage K and V rows (fp16) via cp.async
        #pragma unroll
        for (int i = 0; i < 4; i++) {
            int id = tid + 256 * i;
            int kv = id >> 9;                 // 0=K, 1=V
            int rem = id & 511;
            int row = rem >> 3, ch = rem & 7;
            uint32_t base = kv ? AVF : AKF;
            cpa16(sb + (uint32_t)(base + row * ASTR + ch * 4) * 4,
                  qf + (rowbase + kt * 64 + row) * 1536 + (kv ? 1024 : 512) + qoff + ch * 8);
        }
        asm volatile("cp.async.commit_group;");
        asm volatile("cp.async.wait_group 0;");
        __syncthreads();

        // ---- S = Q K^T (16x64 per warp), 1-term fp16 ----
        float sacc[8][4] = {};
        #pragma unroll
        for (int kk = 0; kk < 4; kk++) {
            #pragma unroll
            for (int pr = 0; pr < 4; pr++) {
                uint32_t bh[4];
                uint32_t bo = (uint32_t)((pr*16 + blr) * ASTR + kk*8 + blw) * 4;
                ldm4(bh, sb + AKF*4 + bo);
                #pragma unroll
                for (int sub = 0; sub < 2; sub++)
                    mma_f16(sacc[pr * 2 + sub], Qf[kk], bh + 2*sub);
            }
        }

        // ---- mask + online softmax ----
        const float scale = 0.125f;
        const bool diag = (kt >= 2 * qt);
        const int row0 = rbase + g, row1 = rbase + g + 8;
        const int colb = kt * 64 + 2 * c;
        float rm0 = -1e30f, rm1 = -1e30f;
        #pragma unroll
        for (int nt = 0; nt < 8; nt++) {
            int c0 = colb + nt * 8;
            float v0 = sacc[nt][0] * scale, v1 = sacc[nt][1] * scale;
            float v2 = sacc[nt][2] * scale, v3 = sacc[nt][3] * scale;
            if (diag) {
                if (c0     > row0) v0 = -1e30f;
                if (c0 + 1 > row0) v1 = -1e30f;
                if (c0     > row1) v2 = -1e30f;
                if (c0 + 1 > row1) v3 = -1e30f;
            }
            sacc[nt][0] = v0; sacc[nt][1] = v1; sacc[nt][2] = v2; sacc[nt][3] = v3;
            rm0 = fmaxf(rm0, fmaxf(v0, v1));
            rm1 = fmaxf(rm1, fmaxf(v2, v3));
        }
        #pragma unroll
        for (int o = 1; o < 4; o <<= 1) {
            rm0 = fmaxf(rm0, __shfl_xor_sync(0xffffffffu, rm0, o));
            rm1 = fmaxf(rm1, __shfl_xor_sync(0xffffffffu, rm1, o));
        }
        float nm0 = fmaxf(m0, rm0), nm1 = fmaxf(m1, rm1);
        float sf0 = __expf(m0 - nm0), sf1 = __expf(m1 - nm1);
        m0 = nm0; m1 = nm1;
        float rs0 = 0.f, rs1 = 0.f;
        #pragma unroll
        for (int nt = 0; nt < 8; nt++) {
            float p0 = __expf(sacc[nt][0] - nm0);
            float p1 = __expf(sacc[nt][1] - nm0);
            float p2 = __expf(sacc[nt][2] - nm1);
            float p3 = __expf(sacc[nt][3] - nm1);
            sacc[nt][0] = p0; sacc[nt][1] = p1; sacc[nt][2] = p2; sacc[nt][3] = p3;
            rs0 += p0 + p1; rs1 += p2 + p3;
        }
        #pragma unroll
        for (int o = 1; o < 4; o <<= 1) {
            rs0 += __shfl_xor_sync(0xffffffffu, rs0, o);
            rs1 += __shfl_xor_sync(0xffffffffu, rs1, o);
        }
        l0 = l0 * sf0 + rs0;
        l1 = l1 * sf1 + rs1;
        #pragma unroll
        for (int nt = 0; nt < 8; nt++) {
            O[nt][0] *= sf0; O[nt][1] *= sf0;
            O[nt][2] *= sf1; O[nt][3] *= sf1;
        }

        // ---- O += P V (P packed fp16 in regs, V via ldmatrix.trans) ----
        #pragma unroll
        for (int kk = 0; kk < 4; kk++) {
            uint32_t ah[4];
            ah[0] = packh2(sacc[2*kk][0],   sacc[2*kk][1]);
            ah[1] = packh2(sacc[2*kk][2],   sacc[2*kk][3]);
            ah[2] = packh2(sacc[2*kk+1][0], sacc[2*kk+1][1]);
            ah[3] = packh2(sacc[2*kk+1][2], sacc[2*kk+1][3]);
            #pragma unroll
            for (int pr = 0; pr < 4; pr++) {
                uint32_t bh[4];
                uint32_t vo = (uint32_t)((kk*16 + vlr) * ASTR + pr*8 + vlw) * 4;
                ldm4t(bh, sb + AVF*4 + vo);
                #pragma unroll
                for (int sub = 0; sub < 2; sub++)
                    mma_f16(O[pr * 2 + sub], ah, bh + 2*sub);
            }
        }
        __syncthreads();
    }

    // ---- epilogue: fp32 accumulators -> bf16 hi/lo planes ----
    float inv0 = 1.0f / l0, inv1 = 1.0f / l1;
    long grow0 = rowbase + rbase + g;
    #pragma unroll
    for (int nt = 0; nt < 8; nt++) {
        int col = qoff + nt * 8 + 2 * c;
        uint32_t hw, lw;
        split2(O[nt][0] * inv0, O[nt][1] * inv0, hw, lw);
        oh[(grow0 * DD + col) >> 1] = hw;
        ol[(grow0 * DD + col) >> 1] = lw;
        split2(O[nt][2] * inv1, O[nt][3] * inv1, hw, lw);
        oh[((grow0 + 8) * DD + col) >> 1] = hw;
        ol[((grow0 + 8) * DD + col) >> 1] = lw;
    }
}

// ---------------------------------------------------------------------------
extern "C" void kernel_launch(void* const* d_in, const int* in_sizes, int n_in,
                              void* d_out, int out_size)
{
    const int*   x    = (const int*)  d_in[0];
    const float* emb  = (const float*)d_in[1];
    const float* pe   = (const float*)d_in[2];
    const float* Wqkv = (const float*)d_in[3];
    const float* Wo   = (const float*)d_in[4];
    const float* bo   = (const float*)d_in[5];
    const float* g1   = (const float*)d_in[6];
    const float* b1   = (const float*)d_in[7];
    const float* g2   = (const float*)d_in[8];
    const float* b2   = (const float*)d_in[9];
    const float* W1   = (const float*)d_in[10];
    const float* bf1  = (const float*)d_in[11];
    const float* W2   = (const float*)d_in[12];
    const float* bf2  = (const float*)d_in[13];
    const float* gf   = (const float*)d_in[14];
    const float* bfp  = (const float*)d_in[15];
    const float* Wout = (const float*)d_in[16];
    const float* bfc  = (const float*)d_in[17];
    float* out = (float*)d_out;

    float *h, *t;
    cudaGetSymbolAddress((void**)&h, g_h);
    cudaGetSymbolAddress((void**)&t, g_t);
    __nv_bfloat16 *hh, *hl, *oh, *ol, *fh, *fl;
    __half *qf, *tf, *outTf;
    cudaGetSymbolAddress((void**)&hh, g_hh);  cudaGetSymbolAddress((void**)&hl, g_hl);
    cudaGetSymbolAddress((void**)&oh, g_oh);  cudaGetSymbolAddress((void**)&ol, g_ol);
    cudaGetSymbolAddress((void**)&fh, g_fh);  cudaGetSymbolAddress((void**)&fl, g_fl);
    cudaGetSymbolAddress((void**)&qf, g_qf);
    cudaGetSymbolAddress((void**)&tf, g_tf);
    cudaGetSymbolAddress((void**)&outTf, g_outT_f);
    __nv_bfloat16 *qkvTh, *qkvTl, *woTh, *woTl, *w1Th, *w1Tl, *w2Th, *w2Tl;
    cudaGetSymbolAddress((void**)&qkvTh, g_qkvT_h);
    cudaGetSymbolAddress((void**)&qkvTl, g_qkvT_l);
    cudaGetSymbolAddress((void**)&woTh,  g_woT_h);
    cudaGetSymbolAddress((void**)&woTl,  g_woT_l);
    cudaGetSymbolAddress((void**)&w1Th,  g_w1T_h);
    cudaGetSymbolAddress((void**)&w1Tl,  g_w1T_l);
    cudaGetSymbolAddress((void**)&w2Th,  g_w2T_h);
    cudaGetSymbolAddress((void**)&w2Tl,  g_w2T_l);

    cudaFuncSetAttribute(attn_f16, cudaFuncAttributeMaxDynamicSharedMemorySize, ATTF_SMEM);
    cudaFuncSetAttribute(gemm_bf16<0,0>, cudaFuncAttributeMaxDynamicSharedMemorySize, GEMM_SMEM);
    cudaFuncSetAttribute(gemm_bf16<0,2>, cudaFuncAttributeMaxDynamicSharedMemorySize, GEMM_SMEM);
    cudaFuncSetAttribute(gemm_bf16<1,1>, cudaFuncAttributeMaxDynamicSharedMemorySize, GEMM_SMEM);
    cudaFuncSetAttribute(gemm_f16, cudaFuncAttributeMaxDynamicSharedMemorySize, F16_SMEM);

    wprep_k<<<dim3(3*DD/32, DD/32, LL), 256>>>(Wqkv, qkvTh, qkvTl, DD, 3*DD);
    wprep_k<<<dim3(DD/32,   DD/32, LL), 256>>>(Wo,   woTh,  woTl,  DD, DD);
    wprep_k<<<dim3(FF/32,   DD/32, LL), 256>>>(W1,   w1Th,  w1Tl,  DD, FF);
    wprep_k<<<dim3(DD/32,   FF/32, LL), 256>>>(W2,   w2Th,  w2Tl,  FF, DD);
    wprep16_k<<<dim3(VV/32, DD/32), 256>>>(Wout, outTf, DD, VV);

    embed_k<<<ROWS, 128>>>(x, emb, pe, h, (uint32_t*)hh, (uint32_t*)hl);

    for (int l = 0; l < LL; l++) {
        // QKV (bf16 3-term internals) -> single fp16 plane
        gemm_bf16<0,2><<<dim3(32, 12), 256, GEMM_SMEM>>>(
            hh, hl, qkvTh + (long)l * 3*DD*DD, qkvTl + (long)l * 3*DD*DD,
            nullptr, nullptr, (uint32_t*)qf, nullptr, ROWS, 3*DD, DD);
        // fp16 1-term attention -> bf16 hi/lo planes
        attn_f16<<<dim3(SS/128, HH, BB), 256, ATTF_SMEM>>>(
            qf, (uint32_t*)oh, (uint32_t*)ol);
        // Wo (bf16 3-term) -> fp32 t
        gemm_bf16<0,0><<<dim3(32, 4), 256, GEMM_SMEM>>>(
            oh, ol, woTh + (long)l * DD*DD, woTl + (long)l * DD*DD,
            bo + l * DD, t, nullptr, nullptr, ROWS, DD, DD);
        add_ln_k<0><<<ROWS, 128>>>(t, h, g1 + l * DD, b1 + l * DD,
                                   h, (uint32_t*)hh, (uint32_t*)hl);
        gemm_bf16<1,1><<<dim3(32, 16), 256, GEMM_SMEM>>>(
            hh, hl, w1Th + (long)l * FF*DD, w1Tl + (long)l * FF*DD,
            bf1 + l * FF, nullptr, (uint32_t*)fh, (uint32_t*)fl, ROWS, FF, DD);
        gemm_bf16<0,0><<<dim3(32, 4), 256, GEMM_SMEM>>>(
            fh, fl, w2Th + (long)l * DD*FF, w2Tl + (long)l * DD*FF,
            bf2 + l * DD, t, nullptr, nullptr, ROWS, DD, FF);
        add_ln_k<0><<<ROWS, 128>>>(t, h, g2 + l * DD, b2 + l * DD,
                                   h, (uint32_t*)hh, (uint32_t*)hl);
    }

    // final LN -> packed fp16 plane
    add_ln_k<1><<<ROWS, 128>>>(h, nullptr, gf, bfp, t, (uint32_t*)tf, nullptr);
    // logits: fp16 single-term GEMM
    gemm_f16<<<dim3(32, 250), 256, F16_SMEM>>>(tf, outTf, bfc, out, ROWS, VV, DD);
}

// round 15
// speedup vs baseline: 3.2541x; 1.4099x over previous
#include <cuda_runtime.h>
#include <cuda_bf16.h>
#include <cuda_fp16.h>
#include <cstdint>

#define BB 2
#define SS 2048
#define DD 512
#define LL 6
#define HH 8
#define FF 2048
#define VV 32000
#define ROWS (BB*SS)   // 4096

// fp32 residual stream scratch
__device__ float g_h [ROWS * DD];
__device__ float g_t [ROWS * DD];
// fp16 activation planes
__device__ __align__(16) __half g_hf [ROWS * DD];
__device__ __align__(16) __half g_qf [ROWS * 3*DD];
__device__ __align__(16) __half g_of [ROWS * DD];
__device__ __align__(16) __half g_ff [ROWS * FF];
__device__ __align__(16) __half g_tf [ROWS * DD];
// fp16 pre-transposed weights [N][K]
__device__ __align__(16) __half g_qkvT_f[LL * 3*DD * DD];
__device__ __align__(16) __half g_woT_f [LL * DD * DD];
__device__ __align__(16) __half g_w1T_f [LL * FF * DD];
__device__ __align__(16) __half g_w2T_f [LL * DD * FF];
__device__ __align__(16) __half g_outT_f[VV * DD];

extern __shared__ char dynsm[];

// ---------------------------------------------------------------------------
__device__ __forceinline__ uint32_t smem_u32(const void* p) {
    uint32_t a;
    asm("{ .reg .u64 t; cvta.to.shared.u64 t, %1; cvt.u32.u64 %0, t; }"
        : "=r"(a) : "l"(p));
    return a;
}
__device__ __forceinline__ void cpa16(uint32_t s, const void* g) {
    asm volatile("cp.async.cg.shared.global [%0], [%1], 16;" :: "r"(s), "l"(g));
}
__device__ __forceinline__ uint32_t packh2(float x0, float x1) {
    __half2 p = __float22half2_rn(make_float2(x0, x1));
    return *(uint32_t*)&p;
}
__device__ __forceinline__ void mma_f16(float* d, const uint32_t* a, const uint32_t* b) {
    asm volatile("mma.sync.aligned.m16n8k16.row.col.f32.f16.f16.f32 "
        "{%0,%1,%2,%3}, {%4,%5,%6,%7}, {%8,%9}, {%0,%1,%2,%3};"
        : "+f"(d[0]), "+f"(d[1]), "+f"(d[2]), "+f"(d[3])
        : "r"(a[0]), "r"(a[1]), "r"(a[2]), "r"(a[3]), "r"(b[0]), "r"(b[1]));
}
__device__ __forceinline__ void ldm4(uint32_t* r, uint32_t a) {
    asm volatile("ldmatrix.sync.aligned.m8n8.x4.shared.b16 {%0,%1,%2,%3}, [%4];"
        : "=r"(r[0]), "=r"(r[1]), "=r"(r[2]), "=r"(r[3]) : "r"(a));
}
__device__ __forceinline__ void ldm4t(uint32_t* r, uint32_t a) {
    asm volatile("ldmatrix.sync.aligned.m8n8.x4.trans.shared.b16 {%0,%1,%2,%3}, [%4];"
        : "=r"(r[0]), "=r"(r[1]), "=r"(r[2]), "=r"(r[3]) : "r"(a));
}

// ---------------------------------------------------------------------------
// Weight prep: W[K,N] fp32 -> WT [N,K] fp16 (transpose), per-matrix via z
// ---------------------------------------------------------------------------
__global__ void wprep16_k(const float* __restrict__ W, __half* __restrict__ o,
                          int K, int N)
{
    __shared__ float ts[32][33];
    long moff = (long)blockIdx.z * K * N;
    int kb = blockIdx.y * 32, nb = blockIdx.x * 32;
    int r = threadIdx.x >> 5, c = threadIdx.x & 31;
    #pragma unroll
    for (int i = 0; i < 4; i++)
        ts[r + i*8][c] = W[moff + (long)(kb + r + i*8) * N + nb + c];
    __syncthreads();
    #pragma unroll
    for (int i = 0; i < 4; i++) {
        int n = r + i*8;
        o[moff + (long)(nb + n) * K + kb + c] = __float2half_rn(ts[c][n]);
    }
}

// ---------------------------------------------------------------------------
// Embedding + PE -> fp32 h + fp16 plane
// ---------------------------------------------------------------------------
__global__ void embed_k(const int* __restrict__ x, const float* __restrict__ emb,
                        const float* __restrict__ pe, float* __restrict__ h,
                        uint32_t* __restrict__ of)
{
    int row = blockIdx.x, tid = threadIdx.x;
    int s   = row & (SS - 1);
    int tok = x[row];
    float4 ev = ((const float4*)(emb + (long)tok * DD))[tid];
    float4 pv = ((const float4*)(pe  + (long)s   * DD))[tid];
    float4 o;
    o.x = ev.x + pv.x; o.y = ev.y + pv.y; o.z = ev.z + pv.z; o.w = ev.w + pv.w;
    ((float4*)(h + (long)row * DD))[tid] = o;
    int wi = row * (DD/2) + tid * 2;
    of[wi]   = packh2(o.x, o.y);
    of[wi+1] = packh2(o.z, o.w);
}

// ---------------------------------------------------------------------------
// out = LayerNorm(x (+ res)) * g + b -> fp32 + fp16 plane
// ---------------------------------------------------------------------------
__global__ void add_ln_k(const float* __restrict__ x, const float* __restrict__ res,
                         const float* __restrict__ gg, const float* __restrict__ bb,
                         float* __restrict__ outF, uint32_t* __restrict__ outP)
{
    int row = blockIdx.x, tid = threadIdx.x;
    float4 v = ((const float4*)(x + (long)row * DD))[tid];
    if (res) {
        float4 rv = ((const float4*)(res + (long)row * DD))[tid];
        v.x += rv.x; v.y += rv.y; v.z += rv.z; v.w += rv.w;
    }
    float s  = v.x + v.y + v.z + v.w;
    float s2 = v.x*v.x + v.y*v.y + v.z*v.z + v.w*v.w;
    #pragma unroll
    for (int o = 16; o; o >>= 1) {
        s  += __shfl_xor_sync(0xffffffffu, s,  o);
        s2 += __shfl_xor_sync(0xffffffffu, s2, o);
    }
    __shared__ float ssum[4], ssq[4];
    int wid = tid >> 5;
    if ((tid & 31) == 0) { ssum[wid] = s; ssq[wid] = s2; }
    __syncthreads();
    s  = ssum[0] + ssum[1] + ssum[2] + ssum[3];
    s2 = ssq[0]  + ssq[1]  + ssq[2]  + ssq[3];
    float mean = s * (1.0f / DD);
    float var  = s2 * (1.0f / DD) - mean * mean;
    float inv  = rsqrtf(var + 1e-5f);
    float4 gv = ((const float4*)gg)[tid];
    float4 bv = ((const float4*)bb)[tid];
    float4 o;
    o.x = (v.x - mean) * inv * gv.x + bv.x;
    o.y = (v.y - mean) * inv * gv.y + bv.y;
    o.z = (v.z - mean) * inv * gv.z + bv.z;
    o.w = (v.w - mean) * inv * gv.w + bv.w;
    ((float4*)(outF + (long)row * DD))[tid] = o;
    int wi = row * (DD/2) + tid * 2;
    outP[wi]   = packh2(o.x, o.y);
    outP[wi+1] = packh2(o.z, o.w);
}

// ---------------------------------------------------------------------------
// fp16 1-term tensor GEMM: C = A[M,K] @ BT[N,K] (+bias)(+relu).
// 256 threads, 64x32 warp tile, BK=32, 2 buffers / 40KB smem,
// one __syncthreads per K-tile. OUTMODE 0: fp32 C. OUTMODE 1: fp16 plane.
// ---------------------------------------------------------------------------
#define GSTR 20
#define GPL  (128*GSTR)
#define F16_SMEM (4*GPL*4)     // 40960 B

template<int RELU, int OUTMODE>
__global__ __launch_bounds__(256)
void gemm_f16(const __half* __restrict__ Ap, const __half* __restrict__ Bp,
              const float* __restrict__ bias,
              float* __restrict__ C, uint32_t* __restrict__ Cf,
              int M, int N, int K)
{
    uint32_t* sm = (uint32_t*)dynsm;
    const int tid = threadIdx.x, warp = tid >> 5, lane = tid & 31;
    const int g = lane >> 2, c = lane & 3;
    const int bm = blockIdx.x * 128, bn = blockIdx.y * 128;
    const int wm = (warp >> 2) * 64, wn = (warp & 3) * 32;
    const uint32_t sb = smem_u32(sm);
    const int T = K / 32;

    const int alr = lane & 15, alw = (lane >> 4) * 4;
    const int blr = (lane & 7) + ((lane >> 4) << 3);
    const int blw = ((lane >> 3) & 1) * 4;

    auto stage = [&](int t, int b) {
        #pragma unroll
        for (int i = 0; i < 2; i++) {
            int id = tid + 256 * i, row = id >> 2, cc = id & 3;
            uint32_t doff = (uint32_t)(row * GSTR + cc * 4) * 4;
            uint32_t dbase = sb + (uint32_t)(b * 2 * GPL) * 4 + doff;
            cpa16(dbase,         Ap + (long)(bm + row) * K + t * 32 + cc * 8);
            cpa16(dbase + GPL*4, Bp + (long)(bn + row) * K + t * 32 + cc * 8);
        }
        asm volatile("cp.async.commit_group;");
    };

    float acc[4][4][4] = {};

    stage(0, 0);

    for (int t = 0; t < T; t++) {
        asm volatile("cp.async.wait_group 0;");
        __syncthreads();
        if (t + 1 < T) stage(t + 1, (t + 1) & 1);

        const uint32_t bufb = sb + (uint32_t)((t & 1) * 2 * GPL) * 4;

        #pragma unroll
        for (int kk = 0; kk < 2; kk++) {
            uint32_t ah[4][4];
            #pragma unroll
            for (int mt = 0; mt < 4; mt++) {
                uint32_t ao = (uint32_t)((wm + mt*16 + alr) * GSTR + kk*8 + alw) * 4;
                ldm4(ah[mt], bufb + ao);
            }
            #pragma unroll
            for (int pr = 0; pr < 2; pr++) {
                uint32_t bh[4];
                uint32_t bo = (uint32_t)((wn + pr*16 + blr) * GSTR + kk*8 + blw) * 4;
                ldm4(bh, bufb + GPL*4 + bo);
                #pragma unroll
                for (int sub = 0; sub < 2; sub++) {
                    int nt = pr * 2 + sub;
                    #pragma unroll
                    for (int mt = 0; mt < 4; mt++)
                        mma_f16(acc[mt][nt], ah[mt], bh + 2*sub);
                }
            }
        }
    }

    #pragma unroll
    for (int mt = 0; mt < 4; mt++) {
        #pragma unroll
        for (int nt = 0; nt < 4; nt++) {
            int col = bn + wn + nt*8 + 2*c;
            float bx = 0.f, by = 0.f;
            if (bias) { bx = bias[col]; by = bias[col + 1]; }
            long r0 = bm + wm + mt*16 + g;
            float v0 = acc[mt][nt][0] + bx, v1 = acc[mt][nt][1] + by;
            float v2 = acc[mt][nt][2] + bx, v3 = acc[mt][nt][3] + by;
            if (RELU) {
                v0 = fmaxf(v0, 0.f); v1 = fmaxf(v1, 0.f);
                v2 = fmaxf(v2, 0.f); v3 = fmaxf(v3, 0.f);
            }
            if (OUTMODE == 0) {
                *(float2*)(C + r0 * N + col)       = make_float2(v0, v1);
                *(float2*)(C + (r0 + 8) * N + col) = make_float2(v2, v3);
            } else {
                Cf[(r0 * N + col) >> 1]       = packh2(v0, v1);
                Cf[((r0 + 8) * N + col) >> 1] = packh2(v2, v3);
            }
        }
    }
}

// ---------------------------------------------------------------------------
// fp16 1-term flash attention (round-14 proven). Output: fp16 plane.
// ---------------------------------------------------------------------------
#define ASTR 36
#define AQF 0
#define AKF (128*ASTR)
#define AVF (AKF + 64*ASTR)
#define ATTF_SMEM ((128*ASTR + 2*64*ASTR)*4)   // 36864 B

__global__ __launch_bounds__(256)
void attn_f16(const __half* __restrict__ qf, uint32_t* __restrict__ of)
{
    uint32_t* sm = (uint32_t*)dynsm;
    const uint32_t sb = smem_u32(sm);
    const int tid = threadIdx.x, warp = tid >> 5, lane = tid & 31;
    const int g = lane >> 2, c = lane & 3;
    const int qt = (int)gridDim.x - 1 - (int)blockIdx.x;
    const int h = blockIdx.y, b = blockIdx.z;
    const long rowbase = (long)b * SS;
    const int qoff = h << 6;

    const int alr = lane & 15, alw = (lane >> 4) * 4;
    const int blr = (lane & 7) + ((lane >> 4) << 3);
    const int blw = ((lane >> 3) & 1) * 4;
    const int vlr = ((lane >> 3) & 1) * 8 + (lane & 7);
    const int vlw = (lane >> 4) * 4;

    #pragma unroll
    for (int i = 0; i < 4; i++) {
        int id = tid + 256 * i;
        int row = id >> 3, ch = id & 7;
        cpa16(sb + (uint32_t)(AQF + row * ASTR + ch * 4) * 4,
              qf + (rowbase + qt * 128 + row) * 1536 + qoff + ch * 8);
    }
    asm volatile("cp.async.commit_group;");
    asm volatile("cp.async.wait_group 0;");
    __syncthreads();

    uint32_t Qf[4][4];
    #pragma unroll
    for (int kk = 0; kk < 4; kk++) {
        uint32_t qo = (uint32_t)((warp*16 + alr) * ASTR + kk*8 + alw) * 4;
        ldm4(Qf[kk], sb + AQF*4 + qo);
    }

    float m0 = -1e30f, m1 = -1e30f, l0 = 0.f, l1 = 0.f;
    float O[8][4] = {};
    const int nk = 2 * qt + 2;
    const int rbase = qt * 128 + warp * 16;

    for (int kt = 0; kt < nk; kt++) {
        #pragma unroll
        for (int i = 0; i < 4; i++) {
            int id = tid + 256 * i;
            int kv = id >> 9;
            int rem = id & 511;
            int row = rem >> 3, ch = rem & 7;
            uint32_t base = kv ? AVF : AKF;
            cpa16(sb + (uint32_t)(base + row * ASTR + ch * 4) * 4,
                  qf + (rowbase + kt * 64 + row) * 1536 + (kv ? 1024 : 512) + qoff + ch * 8);
        }
        asm volatile("cp.async.commit_group;");
        asm volatile("cp.async.wait_group 0;");
        __syncthreads();

        float sacc[8][4] = {};
        #pragma unroll
        for (int kk = 0; kk < 4; kk++) {
            #pragma unroll
            for (int pr = 0; pr < 4; pr++) {
                uint32_t bh[4];
                uint32_t bo = (uint32_t)((pr*16 + blr) * ASTR + kk*8 + blw) * 4;
                ldm4(bh, sb + AKF*4 + bo);
                #pragma unroll
                for (int sub = 0; sub < 2; sub++)
                    mma_f16(sacc[pr * 2 + sub], Qf[kk], bh + 2*sub);
            }
        }

        const float scale = 0.125f;
        const bool diag = (kt >= 2 * qt);
        const int row0 = rbase + g, row1 = rbase + g + 8;
        const int colb = kt * 64 + 2 * c;
        float rm0 = -1e30f, rm1 = -1e30f;
        #pragma unroll
        for (int nt = 0; nt < 8; nt++) {
            int c0 = colb + nt * 8;
            float v0 = sacc[nt][0] * scale, v1 = sacc[nt][1] * scale;
            float v2 = sacc[nt][2] * scale, v3 = sacc[nt][3] * scale;
            if (diag) {
                if (c0     > row0) v0 = -1e30f;
                if (c0 + 1 > row0) v1 = -1e30f;
                if (c0     > row1) v2 = -1e30f;
                if (c0 + 1 > row1) v3 = -1e30f;
            }
            sacc[nt][0] = v0; sacc[nt][1] = v1; sacc[nt][2] = v2; sacc[nt][3] = v3;
            rm0 = fmaxf(rm0, fmaxf(v0, v1));
            rm1 = fmaxf(rm1, fmaxf(v2, v3));
        }
        #pragma unroll
        for (int o = 1; o < 4; o <<= 1) {
            rm0 = fmaxf(rm0, __shfl_xor_sync(0xffffffffu, rm0, o));
            rm1 = fmaxf(rm1, __shfl_xor_sync(0xffffffffu, rm1, o));
        }
        float nm0 = fmaxf(m0, rm0), nm1 = fmaxf(m1, rm1);
        float sf0 = __expf(m0 - nm0), sf1 = __expf(m1 - nm1);
        m0 = nm0; m1 = nm1;
        float rs0 = 0.f, rs1 = 0.f;
        #pragma unroll
        for (int nt = 0; nt < 8; nt++) {
            float p0 = __expf(sacc[nt][0] - nm0);
            float p1 = __expf(sacc[nt][1] - nm0);
            float p2 = __expf(sacc[nt][2] - nm1);
            float p3 = __expf(sacc[nt][3] - nm1);
            sacc[nt][0] = p0; sacc[nt][1] = p1; sacc[nt][2] = p2; sacc[nt][3] = p3;
            rs0 += p0 + p1; rs1 += p2 + p3;
        }
        #pragma unroll
        for (int o = 1; o < 4; o <<= 1) {
            rs0 += __shfl_xor_sync(0xffffffffu, rs0, o);
            rs1 += __shfl_xor_sync(0xffffffffu, rs1, o);
        }
        l0 = l0 * sf0 + rs0;
        l1 = l1 * sf1 + rs1;
        #pragma unroll
        for (int nt = 0; nt < 8; nt++) {
            O[nt][0] *= sf0; O[nt][1] *= sf0;
            O[nt][2] *= sf1; O[nt][3] *= sf1;
        }

        #pragma unroll
        for (int kk = 0; kk < 4; kk++) {
            uint32_t ah[4];
            ah[0] = packh2(sacc[2*kk][0],   sacc[2*kk][1]);
            ah[1] = packh2(sacc[2*kk][2],   sacc[2*kk][3]);
            ah[2] = packh2(sacc[2*kk+1][0], sacc[2*kk+1][1]);
            ah[3] = packh2(sacc[2*kk+1][2], sacc[2*kk+1][3]);
            #pragma unroll
            for (int pr = 0; pr < 4; pr++) {
                uint32_t bh[4];
                uint32_t vo = (uint32_t)((kk*16 + vlr) * ASTR + pr*8 + vlw) * 4;
                ldm4t(bh, sb + AVF*4 + vo);
                #pragma unroll
                for (int sub = 0; sub < 2; sub++)
                    mma_f16(O[pr * 2 + sub], ah, bh + 2*sub);
            }
        }
        __syncthreads();
    }

    float inv0 = 1.0f / l0, inv1 = 1.0f / l1;
    long grow0 = rowbase + rbase + g;
    #pragma unroll
    for (int nt = 0; nt < 8; nt++) {
        int col = qoff + nt * 8 + 2 * c;
        of[(grow0 * DD + col) >> 1]       = packh2(O[nt][0] * inv0, O[nt][1] * inv0);
        of[((grow0 + 8) * DD + col) >> 1] = packh2(O[nt][2] * inv1, O[nt][3] * inv1);
    }
}

// ---------------------------------------------------------------------------
extern "C" void kernel_launch(void* const* d_in, const int* in_sizes, int n_in,
                              void* d_out, int out_size)
{
    const int*   x    = (const int*)  d_in[0];
    const float* emb  = (const float*)d_in[1];
    const float* pe   = (const float*)d_in[2];
    const float* Wqkv = (const float*)d_in[3];
    const float* Wo   = (const float*)d_in[4];
    const float* bo   = (const float*)d_in[5];
    const float* g1   = (const float*)d_in[6];
    const float* b1   = (const float*)d_in[7];
    const float* g2   = (const float*)d_in[8];
    const float* b2   = (const float*)d_in[9];
    const float* W1   = (const float*)d_in[10];
    const float* bf1  = (const float*)d_in[11];
    const float* W2   = (const float*)d_in[12];
    const float* bf2  = (const float*)d_in[13];
    const float* gf   = (const float*)d_in[14];
    const float* bfp  = (const float*)d_in[15];
    const float* Wout = (const float*)d_in[16];
    const float* bfc  = (const float*)d_in[17];
    float* out = (float*)d_out;

    float *h, *t;
    cudaGetSymbolAddress((void**)&h, g_h);
    cudaGetSymbolAddress((void**)&t, g_t);
    __half *hf, *qf, *of, *ff, *tf;
    cudaGetSymbolAddress((void**)&hf, g_hf);
    cudaGetSymbolAddress((void**)&qf, g_qf);
    cudaGetSymbolAddress((void**)&of, g_of);
    cudaGetSymbolAddress((void**)&ff, g_ff);
    cudaGetSymbolAddress((void**)&tf, g_tf);
    __half *qkvTf, *woTf, *w1Tf, *w2Tf, *outTf;
    cudaGetSymbolAddress((void**)&qkvTf, g_qkvT_f);
    cudaGetSymbolAddress((void**)&woTf,  g_woT_f);
    cudaGetSymbolAddress((void**)&w1Tf,  g_w1T_f);
    cudaGetSymbolAddress((void**)&w2Tf,  g_w2T_f);
    cudaGetSymbolAddress((void**)&outTf, g_outT_f);

    cudaFuncSetAttribute(attn_f16, cudaFuncAttributeMaxDynamicSharedMemorySize, ATTF_SMEM);
    cudaFuncSetAttribute(gemm_f16<0,0>, cudaFuncAttributeMaxDynamicSharedMemorySize, F16_SMEM);
    cudaFuncSetAttribute(gemm_f16<0,1>, cudaFuncAttributeMaxDynamicSharedMemorySize, F16_SMEM);
    cudaFuncSetAttribute(gemm_f16<1,1>, cudaFuncAttributeMaxDynamicSharedMemorySize, F16_SMEM);

    wprep16_k<<<dim3(3*DD/32, DD/32, LL), 256>>>(Wqkv, qkvTf, DD, 3*DD);
    wprep16_k<<<dim3(DD/32,   DD/32, LL), 256>>>(Wo,   woTf,  DD, DD);
    wprep16_k<<<dim3(FF/32,   DD/32, LL), 256>>>(W1,   w1Tf,  DD, FF);
    wprep16_k<<<dim3(DD/32,   FF/32, LL), 256>>>(W2,   w2Tf,  FF, DD);
    wprep16_k<<<dim3(VV/32,   DD/32, 1 ), 256>>>(Wout, outTf, DD, VV);

    embed_k<<<ROWS, 128>>>(x, emb, pe, h, (uint32_t*)hf);

    for (int l = 0; l < LL; l++) {
        // QKV -> fp16 plane
        gemm_f16<0,1><<<dim3(32, 12), 256, F16_SMEM>>>(
            hf, qkvTf + (long)l * 3*DD*DD, nullptr,
            nullptr, (uint32_t*)qf, ROWS, 3*DD, DD);
        // attention -> fp16 plane
        attn_f16<<<dim3(SS/128, HH, BB), 256, ATTF_SMEM>>>(qf, (uint32_t*)of);
        // Wo -> fp32 t
        gemm_f16<0,0><<<dim3(32, 4), 256, F16_SMEM>>>(
            of, woTf + (long)l * DD*DD, bo + l * DD,
            t, nullptr, ROWS, DD, DD);
        add_ln_k<<<ROWS, 128>>>(t, h, g1 + l * DD, b1 + l * DD, h, (uint32_t*)hf);
        // FF1 + relu -> fp16 plane
        gemm_f16<1,1><<<dim3(32, 16), 256, F16_SMEM>>>(
            hf, w1Tf + (long)l * FF*DD, bf1 + l * FF,
            nullptr, (uint32_t*)ff, ROWS, FF, DD);
        // FF2 -> fp32 t
        gemm_f16<0,0><<<dim3(32, 4), 256, F16_SMEM>>>(
            ff, w2Tf + (long)l * DD*FF, bf2 + l * DD,
            t, nullptr, ROWS, DD, FF);
        add_ln_k<<<ROWS, 128>>>(t, h, g2 + l * DD, b2 + l * DD, h, (uint32_t*)hf);
    }

    add_ln_k<<<ROWS, 128>>>(h, nullptr, gf, bfp, t, (uint32_t*)tf);
    gemm_f16<0,0><<<dim3(32, 250), 256, F16_SMEM>>>(
        tf, outTf, bfc, out, nullptr, ROWS, VV, DD);
}